// round 8
// baseline (speedup 1.0000x reference)
#include <cuda_runtime.h>
#include <cuda_bf16.h>
#include <cstdint>

#define NPTS 4096
#define KNB  32
#define BMAX 4

typedef unsigned long long ull;

// ---------------- f32x2 helpers (feat kernel) ----------------
__device__ __forceinline__ ull pack2(float lo, float hi) {
    ull r; asm("mov.b64 %0, {%1, %2};" : "=l"(r) : "f"(lo), "f"(hi)); return r;
}
__device__ __forceinline__ ull ffma2(ull a, ull b, ull c) {
    ull d; asm("fma.rn.f32x2 %0, %1, %2, %3;" : "=l"(d) : "l"(a), "l"(b), "l"(c));
    return d;
}
__device__ __forceinline__ float2 unpack2(ull v) {
    float lo, hi; asm("mov.b64 {%0, %1}, %2;" : "=f"(lo), "=f"(hi) : "l"(v));
    return make_float2(lo, hi);
}

// ---------------- tf32 split helpers ----------------
__device__ __forceinline__ void split_tf32(float v, uint32_t& h, uint32_t& l) {
    const uint32_t hb = __float_as_uint(v) & 0xFFFFE000u;   // exact tf32
    const float lo = v - __uint_as_float(hb);
    uint32_t lb; asm("cvt.rna.tf32.f32 %0, %1;" : "=r"(lb) : "f"(lo));
    h = hb; l = lb;
}

__device__ __forceinline__ void mma_tf32(float* c, const uint32_t* a, const uint32_t* b) {
    asm volatile(
        "mma.sync.aligned.m16n8k8.row.col.f32.tf32.tf32.f32 "
        "{%0,%1,%2,%3}, {%4,%5,%6,%7}, {%8,%9}, {%0,%1,%2,%3};"
        : "+f"(c[0]), "+f"(c[1]), "+f"(c[2]), "+f"(c[3])
        : "r"(a[0]), "r"(a[1]), "r"(a[2]), "r"(a[3]), "r"(b[0]), "r"(b[1]));
}

// ---------------- scratch ----------------
__device__ __align__(16) int   g_idx    [BMAX * NPTS * KNB];
__device__ __align__(16) float g_feat   [(size_t)3 * BMAX * NPTS * 128];
__device__ __align__(16) float g_point_t[(size_t)BMAX * NPTS * 384];
__device__ __align__(16) float g_gf0_t  [(size_t)BMAX * NPTS * 256];
__device__ __align__(16) float g_gf_t   [(size_t)BMAX * NPTS * 1024];
__device__ __align__(16) float g_msf0_t [(size_t)BMAX * NPTS * 256];
__device__ __align__(16) float g_msf_t  [(size_t)BMAX * NPTS * 128];

// =================================================================
// K1: KNN — warp per query, lane-distributed sorted top-32 list
// =================================================================
__global__ __launch_bounds__(256) void knn_kernel(const float* __restrict__ x,
                                                  int* __restrict__ idx)
{
    __shared__ float4 tile[1024];
    const int b = blockIdx.y;
    const int tid = threadIdx.x;
    const int w = tid >> 5, lane = tid & 31;
    const int q = blockIdx.x * 8 + w;
    const float* xb = x + (size_t)b * 3 * NPTS;

    const float qx = xb[q], qy = xb[NPTS + q], qz = xb[2 * NPTS + q];
    const float qsq = qx * qx + qy * qy + qz * qz;

    float v = 3.0e38f;
    int   vi = 0x7fffffff;
    float cm = 3.0e38f;

    for (int t0 = 0; t0 < NPTS; t0 += 1024) {
        __syncthreads();
        for (int i = tid; i < 1024; i += 256) {
            const int g = t0 + i;
            const float cx = xb[g], cy = xb[NPTS + g], cz = xb[2 * NPTS + g];
            tile[i] = make_float4(cx, cy, cz, cx * cx + cy * cy + cz * cz);
        }
        __syncthreads();

        for (int c = 0; c < 32; c++) {
            const int gbase = t0 + c * 32;
            const float4 p = tile[c * 32 + lane];
            float d = qsq + p.w - 2.0f * fmaf(qx, p.x, fmaf(qy, p.y, qz * p.z));
            if (gbase + lane == q) d = 3.0e38f;

            unsigned m = __ballot_sync(0xffffffffu, d < cm);
            while (m) {
                const int src = __ffs(m) - 1; m &= m - 1;
                const float dd = __shfl_sync(0xffffffffu, d, src);
                const int   ii = gbase + src;
                const unsigned less = __ballot_sync(0xffffffffu,
                        (v < dd) || (v == dd && vi < ii));
                const int pos = __popc(less);
                const float pv = __shfl_up_sync(0xffffffffu, v, 1);
                const int   pi = __shfl_up_sync(0xffffffffu, vi, 1);
                if (pos < 32) {
                    if (lane == pos)      { v = dd; vi = ii; }
                    else if (lane > pos)  { v = pv; vi = pi; }
                }
                cm = __shfl_sync(0xffffffffu, v, 31);
            }
        }
    }
    idx[((size_t)b * NPTS + q) * KNB + lane] = vi;
}

// =================================================================
// K2: per-point 3-layer MLP (3->64->64->128), f32x2 packed math.
// =================================================================
#define SMEM_FEAT_FLOATS (192 + 64 + 4096 + 64 + 8192 + 128)
#define SMEM_FEAT_BYTES  (SMEM_FEAT_FLOATS * 4)

__global__ __launch_bounds__(128) void feat_kernel(
    const float* __restrict__ x,
    const float* __restrict__ sW0, const float* __restrict__ sb0,
    const float* __restrict__ sW1, const float* __restrict__ sb1,
    const float* __restrict__ sW2, const float* __restrict__ sb2,
    float* __restrict__ feat, int B)
{
    extern __shared__ float sm[];
    float* w0s = sm;
    float* b0s = w0s + 192;
    float* w1s = b0s + 64;
    float* b1s = w1s + 4096;
    float* w2s = b1s + 64;
    float* b2s = w2s + 8192;

    const int s = blockIdx.y, b = blockIdx.z;
    const int tid = threadIdx.x;

    for (int i = tid; i < 192;  i += 128) w0s[i] = sW0[s * 192 + i];
    for (int i = tid; i < 64;   i += 128) { b0s[i] = sb0[s * 64 + i]; b1s[i] = sb1[s * 64 + i]; }
    for (int i = tid; i < 4096; i += 128) w1s[i] = sW1[s * 4096 + i];
    for (int i = tid; i < 8192; i += 128) w2s[i] = sW2[s * 8192 + i];
    for (int i = tid; i < 128;  i += 128) b2s[i] = sb2[s * 128 + i];
    __syncthreads();

    const int j = blockIdx.x * 128 + tid;
    const float* xb = x + (size_t)b * 3 * NPTS;
    const float px = xb[j], py = xb[NPTS + j], pz = xb[2 * NPTS + j];

    float h0[64];
#pragma unroll
    for (int o = 0; o < 64; o++) {
        float a = fmaf(w0s[o * 3 + 2], pz,
                  fmaf(w0s[o * 3 + 1], py,
                  fmaf(w0s[o * 3 + 0], px, b0s[o])));
        h0[o] = fmaxf(a, 0.0f);
    }

    ull hp[32];
#pragma unroll
    for (int c = 0; c < 32; c++) hp[c] = pack2(h0[2 * c], h0[2 * c + 1]);

    float h1[64];
#pragma unroll
    for (int o = 0; o < 64; o += 2) {
        ull a0 = 0ull, a1 = 0ull;
        const ull* r0 = (const ull*)(w1s + (o    ) * 64);
        const ull* r1 = (const ull*)(w1s + (o + 1) * 64);
#pragma unroll
        for (int c = 0; c < 32; c++) {
            a0 = ffma2(r0[c], hp[c], a0);
            a1 = ffma2(r1[c], hp[c], a1);
        }
        const float2 u0 = unpack2(a0), u1 = unpack2(a1);
        h1[o]     = fmaxf(u0.x + u0.y + b1s[o],     0.0f);
        h1[o + 1] = fmaxf(u1.x + u1.y + b1s[o + 1], 0.0f);
    }

#pragma unroll
    for (int c = 0; c < 32; c++) hp[c] = pack2(h1[2 * c], h1[2 * c + 1]);

    float* fout = feat + ((size_t)(s * B + b) * NPTS + j) * 128;
    for (int o = 0; o < 128; o += 4) {
        ull a0 = 0ull, a1 = 0ull, a2 = 0ull, a3 = 0ull;
        const ull* r0 = (const ull*)(w2s + (size_t)(o    ) * 64);
        const ull* r1 = (const ull*)(w2s + (size_t)(o + 1) * 64);
        const ull* r2 = (const ull*)(w2s + (size_t)(o + 2) * 64);
        const ull* r3 = (const ull*)(w2s + (size_t)(o + 3) * 64);
#pragma unroll
        for (int c = 0; c < 32; c++) {
            a0 = ffma2(r0[c], hp[c], a0);
            a1 = ffma2(r1[c], hp[c], a1);
            a2 = ffma2(r2[c], hp[c], a2);
            a3 = ffma2(r3[c], hp[c], a3);
        }
        const float2 u0 = unpack2(a0), u1 = unpack2(a1);
        const float2 u2 = unpack2(a2), u3 = unpack2(a3);
        float4 o4;
        o4.x = fmaxf(u0.x + u0.y + b2s[o],     0.0f);
        o4.y = fmaxf(u1.x + u1.y + b2s[o + 1], 0.0f);
        o4.z = fmaxf(u2.x + u2.y + b2s[o + 2], 0.0f);
        o4.w = fmaxf(u3.x + u3.y + b2s[o + 3], 0.0f);
        *(float4*)(fout + o) = o4;
    }
}

// =================================================================
// K3: gather-max over 32 neighbors -> point_t[b][n][384]
// =================================================================
__global__ __launch_bounds__(256) void maxpool_kernel(
    const float* __restrict__ feat, const int* __restrict__ idx,
    float* __restrict__ point_t, int B)
{
    const int s = blockIdx.y, b = blockIdx.z;
    const int tid = threadIdx.x;
    const int w = tid >> 5, lane = tid & 31;
    const int n = blockIdx.x * 8 + w;

    const int ki = idx[((size_t)b * NPTS + n) * KNB + lane];
    const float* fb = feat + (size_t)(s * B + b) * NPTS * 128;

    float4 m = make_float4(-3.0e38f, -3.0e38f, -3.0e38f, -3.0e38f);
#pragma unroll
    for (int k = 0; k < KNB; k++) {
        const int j = __shfl_sync(0xffffffffu, ki, k);
        const float4 vv = *(const float4*)(fb + (size_t)j * 128 + lane * 4);
        m.x = fmaxf(m.x, vv.x); m.y = fmaxf(m.y, vv.y);
        m.z = fmaxf(m.z, vv.z); m.w = fmaxf(m.w, vv.w);
    }
    *(float4*)(point_t + ((size_t)b * NPTS + n) * 384 + s * 128 + lane * 4) = m;
}

// =================================================================
// K4: mma.sync tf32 GEMM, 3xTF32 split (fp32-accurate).
// Y_t[b][n][m] = relu( W[M,K] @ X_t[b][n][K]^T + bias )
// CTA tile 128(M) x 128(N), 8 warps (warp tile 64x32), k-chunk 16.
// smem k-major [split][k][dim] with pad; register prefetch of next
// chunk overlaps global latency with MMA.
// =================================================================
#define KCH 16
#define SDIM 132

__global__ __launch_bounds__(256) void gemm_mma(
    const float* __restrict__ W, const float* __restrict__ bias,
    const float* __restrict__ X, float* __restrict__ Y, int M, int K)
{
    __shared__ uint32_t sA[2][KCH][SDIM];
    __shared__ uint32_t sB[2][KCH][SDIM];

    const int tid = threadIdx.x, wid = tid >> 5, lane = tid & 31;
    const int wm = wid & 1, wn = wid >> 1;           // 2 x 4 warp grid
    const int m0 = blockIdx.x * 128, n0 = blockIdx.y * 128;
    const int bi = blockIdx.z;
    const float* Xb = X + (size_t)bi * NPTS * K;

    // per-thread load coords: row = tid>>1 (0..127), k-half = (tid&1)*8
    const int lrow = tid >> 1;
    const int lkq  = (tid & 1) << 3;

    float acc[4][4][4];
#pragma unroll
    for (int i = 0; i < 4; i++)
#pragma unroll
        for (int j = 0; j < 4; j++)
#pragma unroll
            for (int r = 0; r < 4; r++) acc[i][j][r] = 0.0f;

    const int nch = K / KCH;

    // prefetch chunk 0
    float4 pa0, pa1, pb0, pb1;
    {
        const float* wp = W + (size_t)(m0 + lrow) * K + lkq;
        const float* xp = Xb + (size_t)(n0 + lrow) * K + lkq;
        pa0 = *(const float4*)(wp);     pa1 = *(const float4*)(wp + 4);
        pb0 = *(const float4*)(xp);     pb1 = *(const float4*)(xp + 4);
    }

    for (int ch = 0; ch < nch; ch++) {
        // split + store prefetched chunk into smem
        {
            const float a[8] = {pa0.x, pa0.y, pa0.z, pa0.w, pa1.x, pa1.y, pa1.z, pa1.w};
            const float b[8] = {pb0.x, pb0.y, pb0.z, pb0.w, pb1.x, pb1.y, pb1.z, pb1.w};
#pragma unroll
            for (int j = 0; j < 8; j++) {
                uint32_t h, l;
                split_tf32(a[j], h, l);
                sA[0][lkq + j][lrow] = h; sA[1][lkq + j][lrow] = l;
                split_tf32(b[j], h, l);
                sB[0][lkq + j][lrow] = h; sB[1][lkq + j][lrow] = l;
            }
        }
        __syncthreads();

        // prefetch next chunk (overlaps with MMA below)
        if (ch + 1 < nch) {
            const int k0 = (ch + 1) * KCH;
            const float* wp = W + (size_t)(m0 + lrow) * K + k0 + lkq;
            const float* xp = Xb + (size_t)(n0 + lrow) * K + k0 + lkq;
            pa0 = *(const float4*)(wp);     pa1 = *(const float4*)(wp + 4);
            pb0 = *(const float4*)(xp);     pb1 = *(const float4*)(xp + 4);
        }

        const int g = lane >> 2, t = lane & 3;
#pragma unroll
        for (int ks = 0; ks < 2; ks++) {
            const int kb = ks * 8;
            uint32_t ah[4][4], al[4][4], bh[4][2], bl[4][2];
#pragma unroll
            for (int mi = 0; mi < 4; mi++) {
                const int m = wm * 64 + mi * 16;
                ah[mi][0] = sA[0][kb + t    ][m + g];
                ah[mi][1] = sA[0][kb + t    ][m + g + 8];
                ah[mi][2] = sA[0][kb + t + 4][m + g];
                ah[mi][3] = sA[0][kb + t + 4][m + g + 8];
                al[mi][0] = sA[1][kb + t    ][m + g];
                al[mi][1] = sA[1][kb + t    ][m + g + 8];
                al[mi][2] = sA[1][kb + t + 4][m + g];
                al[mi][3] = sA[1][kb + t + 4][m + g + 8];
            }
#pragma unroll
            for (int ni = 0; ni < 4; ni++) {
                const int n = wn * 32 + ni * 8;
                bh[ni][0] = sB[0][kb + t    ][n + g];
                bh[ni][1] = sB[0][kb + t + 4][n + g];
                bl[ni][0] = sB[1][kb + t    ][n + g];
                bl[ni][1] = sB[1][kb + t + 4][n + g];
            }
#pragma unroll
            for (int mi = 0; mi < 4; mi++)
#pragma unroll
                for (int ni = 0; ni < 4; ni++) {
                    mma_tf32(acc[mi][ni], ah[mi], bh[ni]);
                    mma_tf32(acc[mi][ni], ah[mi], bl[ni]);
                    mma_tf32(acc[mi][ni], al[mi], bh[ni]);
                }
        }
        __syncthreads();
    }

    // epilogue: D[m][n] held as c0:(g, 2t) c1:(g, 2t+1) c2:(g+8, 2t) c3:(g+8, 2t+1)
    const int g = lane >> 2, t2 = (lane & 3) * 2;
#pragma unroll
    for (int mi = 0; mi < 4; mi++) {
        const int mlo = m0 + wm * 64 + mi * 16 + g;
        const float bv0 = bias[mlo], bv1 = bias[mlo + 8];
#pragma unroll
        for (int ni = 0; ni < 4; ni++) {
            const int n = n0 + wn * 32 + ni * 8 + t2;
            float* y0 = Y + ((size_t)bi * NPTS + n) * M;
            float* y1 = y0 + M;
            y0[mlo]     = fmaxf(acc[mi][ni][0] + bv0, 0.0f);
            y1[mlo]     = fmaxf(acc[mi][ni][1] + bv0, 0.0f);
            y0[mlo + 8] = fmaxf(acc[mi][ni][2] + bv1, 0.0f);
            y1[mlo + 8] = fmaxf(acc[mi][ni][3] + bv1, 0.0f);
        }
    }
}

// =================================================================
// rowmax over n for gf_t[b][n][1024] -> out[b][1024]
// =================================================================
__global__ __launch_bounds__(256) void rowmax_t_kernel(const float* __restrict__ gf,
                                                       float* __restrict__ out)
{
    const int c = blockIdx.x * 256 + threadIdx.x;
    const int b = blockIdx.y;
    const float* p = gf + (size_t)b * NPTS * 1024 + c;
    float m0 = -3.0e38f, m1 = -3.0e38f, m2 = -3.0e38f, m3 = -3.0e38f;
    float m4 = -3.0e38f, m5 = -3.0e38f, m6 = -3.0e38f, m7 = -3.0e38f;
    for (int n = 0; n < NPTS; n += 8) {
        m0 = fmaxf(m0, p[(size_t)(n    ) * 1024]);
        m1 = fmaxf(m1, p[(size_t)(n + 1) * 1024]);
        m2 = fmaxf(m2, p[(size_t)(n + 2) * 1024]);
        m3 = fmaxf(m3, p[(size_t)(n + 3) * 1024]);
        m4 = fmaxf(m4, p[(size_t)(n + 4) * 1024]);
        m5 = fmaxf(m5, p[(size_t)(n + 5) * 1024]);
        m6 = fmaxf(m6, p[(size_t)(n + 6) * 1024]);
        m7 = fmaxf(m7, p[(size_t)(n + 7) * 1024]);
    }
    m0 = fmaxf(fmaxf(m0, m1), fmaxf(m2, m3));
    m4 = fmaxf(fmaxf(m4, m5), fmaxf(m6, m7));
    out[(size_t)b * 1024 + c] = fmaxf(m0, m4);
}

// =================================================================
// transpose msf_t[b][n][128] -> out[b][128][n]
// =================================================================
__global__ void transpose_msf(const float* __restrict__ in, float* __restrict__ out)
{
    __shared__ float t[32][33];
    const int b = blockIdx.z;
    const int n0 = blockIdx.x * 32, c0 = blockIdx.y * 32;
    const int tx = threadIdx.x, ty = threadIdx.y;   // 32 x 8
#pragma unroll
    for (int r = 0; r < 32; r += 8)
        t[ty + r][tx] = in[(size_t)((size_t)b * NPTS + n0 + ty + r) * 128 + c0 + tx];
    __syncthreads();
#pragma unroll
    for (int r = 0; r < 32; r += 8)
        out[(size_t)((size_t)b * 128 + c0 + ty + r) * NPTS + n0 + tx] = t[tx][ty + r];
}

// =================================================================
extern "C" void kernel_launch(void* const* d_in, const int* in_sizes, int n_in,
                              void* d_out, int out_size)
{
    const float* x   = (const float*)d_in[0];
    const float* sW0 = (const float*)d_in[1];
    const float* sb0 = (const float*)d_in[2];
    const float* sW1 = (const float*)d_in[3];
    const float* sb1 = (const float*)d_in[4];
    const float* sW2 = (const float*)d_in[5];
    const float* sb2 = (const float*)d_in[6];
    const float* gW0 = (const float*)d_in[7];
    const float* gb0 = (const float*)d_in[8];
    const float* gW1 = (const float*)d_in[9];
    const float* gb1 = (const float*)d_in[10];
    const float* mW0 = (const float*)d_in[11];
    const float* mb0 = (const float*)d_in[12];
    const float* mW1 = (const float*)d_in[13];
    const float* mb1 = (const float*)d_in[14];

    const int B = in_sizes[0] / (3 * NPTS);
    float* out = (float*)d_out;

    void *p_idx, *p_feat, *p_point, *p_gf0, *p_gf, *p_msf0, *p_msf;
    cudaGetSymbolAddress(&p_idx,   g_idx);
    cudaGetSymbolAddress(&p_feat,  g_feat);
    cudaGetSymbolAddress(&p_point, g_point_t);
    cudaGetSymbolAddress(&p_gf0,   g_gf0_t);
    cudaGetSymbolAddress(&p_gf,    g_gf_t);
    cudaGetSymbolAddress(&p_msf0,  g_msf0_t);
    cudaGetSymbolAddress(&p_msf,   g_msf_t);

    cudaFuncSetAttribute(feat_kernel,
                         cudaFuncAttributeMaxDynamicSharedMemorySize, SMEM_FEAT_BYTES);

    // 1) KNN
    knn_kernel<<<dim3(NPTS / 8, B), 256>>>(x, (int*)p_idx);

    // 2) per-point MLP features
    feat_kernel<<<dim3(NPTS / 128, 3, B), 128, SMEM_FEAT_BYTES>>>(
        x, sW0, sb0, sW1, sb1, sW2, sb2, (float*)p_feat, B);

    // 3) gather-max -> point_t[b][n][384]
    maxpool_kernel<<<dim3(NPTS / 8, 3, B), 256>>>(
        (const float*)p_feat, (const int*)p_idx, (float*)p_point, B);

    // 4) gf0_t[b][n][256] = relu(gW0 @ point)   M=256,K=384
    gemm_mma<<<dim3(256 / 128, NPTS / 128, B), 256>>>(
        gW0, gb0, (const float*)p_point, (float*)p_gf0, 256, 384);

    // 5) gf_t[b][n][1024] = relu(gW1 @ gf0)     M=1024,K=256
    gemm_mma<<<dim3(1024 / 128, NPTS / 128, B), 256>>>(
        gW1, gb1, (const float*)p_gf0, (float*)p_gf, 1024, 256);

    // 6) global_feature -> d_out[0 : B*1024]
    rowmax_t_kernel<<<dim3(1024 / 256, B), 256>>>((const float*)p_gf, out);

    // 7) msf0_t[b][n][256] = relu(mW0 @ gf)     M=256,K=1024
    gemm_mma<<<dim3(256 / 128, NPTS / 128, B), 256>>>(
        mW0, mb0, (const float*)p_gf, (float*)p_msf0, 256, 1024);

    // 8) msf_t[b][n][128] = relu(mW1 @ msf0)    M=128,K=256
    gemm_mma<<<dim3(128 / 128, NPTS / 128, B), 256>>>(
        mW1, mb1, (const float*)p_msf0, (float*)p_msf, 128, 256);

    // 9) transpose -> d_out[B*1024 : ] as [B,128,N]
    transpose_msf<<<dim3(NPTS / 32, 128 / 32, B), dim3(32, 8)>>>(
        (const float*)p_msf, out + (size_t)B * 1024);
}

// round 9
// speedup vs baseline: 1.2022x; 1.2022x over previous
#include <cuda_runtime.h>
#include <cuda_bf16.h>
#include <cstdint>

#define NPTS 4096
#define KNB  32
#define BMAX 4

typedef unsigned long long ull;

// ---------------- f32x2 helpers (feat kernel) ----------------
__device__ __forceinline__ ull pack2(float lo, float hi) {
    ull r; asm("mov.b64 %0, {%1, %2};" : "=l"(r) : "f"(lo), "f"(hi)); return r;
}
__device__ __forceinline__ ull ffma2(ull a, ull b, ull c) {
    ull d; asm("fma.rn.f32x2 %0, %1, %2, %3;" : "=l"(d) : "l"(a), "l"(b), "l"(c));
    return d;
}
__device__ __forceinline__ float2 unpack2(ull v) {
    float lo, hi; asm("mov.b64 {%0, %1}, %2;" : "=f"(lo), "=f"(hi) : "l"(v));
    return make_float2(lo, hi);
}

// ---------------- tf32 split + mma helpers ----------------
__device__ __forceinline__ void split_tf32(float v, uint32_t& h, uint32_t& l) {
    const uint32_t hb = __float_as_uint(v) & 0xFFFFE000u;   // exact tf32
    const float lo = v - __uint_as_float(hb);
    uint32_t lb; asm("cvt.rna.tf32.f32 %0, %1;" : "=r"(lb) : "f"(lo));
    h = hb; l = lb;
}
__device__ __forceinline__ void mma_tf32(float* c, const uint32_t* a, const uint32_t* b) {
    asm volatile(
        "mma.sync.aligned.m16n8k8.row.col.f32.tf32.tf32.f32 "
        "{%0,%1,%2,%3}, {%4,%5,%6,%7}, {%8,%9}, {%0,%1,%2,%3};"
        : "+f"(c[0]), "+f"(c[1]), "+f"(c[2]), "+f"(c[3])
        : "r"(a[0]), "r"(a[1]), "r"(a[2]), "r"(a[3]), "r"(b[0]), "r"(b[1]));
}
__device__ __forceinline__ void ldsm4(uint32_t& r0, uint32_t& r1, uint32_t& r2, uint32_t& r3,
                                      uint32_t addr) {
    asm volatile("ldmatrix.sync.aligned.m8n8.x4.shared.b16 {%0,%1,%2,%3}, [%4];"
                 : "=r"(r0), "=r"(r1), "=r"(r2), "=r"(r3) : "r"(addr));
}
__device__ __forceinline__ uint32_t smem_u32(const void* p) {
    uint32_t a;
    asm("{ .reg .u64 t; cvta.to.shared.u64 t, %1; cvt.u32.u64 %0, t; }" : "=r"(a) : "l"(p));
    return a;
}

// ---------------- scratch ----------------
__device__ __align__(16) int   g_idx    [BMAX * NPTS * KNB];
__device__ __align__(16) float g_feat   [(size_t)3 * BMAX * NPTS * 128];
__device__ __align__(16) float g_point_t[(size_t)BMAX * NPTS * 384];
__device__ __align__(16) float g_gf0_t  [(size_t)BMAX * NPTS * 256];
__device__ __align__(16) float g_gf_t   [(size_t)BMAX * NPTS * 1024];
__device__ __align__(16) float g_msf0_t [(size_t)BMAX * NPTS * 256];
__device__ __align__(16) float g_msf_t  [(size_t)BMAX * NPTS * 128];

// =================================================================
// K1: KNN — warp per query, lane-distributed sorted top-32 list
// =================================================================
__global__ __launch_bounds__(256) void knn_kernel(const float* __restrict__ x,
                                                  int* __restrict__ idx)
{
    __shared__ float4 tile[1024];
    const int b = blockIdx.y;
    const int tid = threadIdx.x;
    const int w = tid >> 5, lane = tid & 31;
    const int q = blockIdx.x * 8 + w;
    const float* xb = x + (size_t)b * 3 * NPTS;

    const float qx = xb[q], qy = xb[NPTS + q], qz = xb[2 * NPTS + q];
    const float qsq = qx * qx + qy * qy + qz * qz;

    float v = 3.0e38f;
    int   vi = 0x7fffffff;
    float cm = 3.0e38f;

    for (int t0 = 0; t0 < NPTS; t0 += 1024) {
        __syncthreads();
        for (int i = tid; i < 1024; i += 256) {
            const int g = t0 + i;
            const float cx = xb[g], cy = xb[NPTS + g], cz = xb[2 * NPTS + g];
            tile[i] = make_float4(cx, cy, cz, cx * cx + cy * cy + cz * cz);
        }
        __syncthreads();

        for (int c = 0; c < 32; c++) {
            const int gbase = t0 + c * 32;
            const float4 p = tile[c * 32 + lane];
            float d = qsq + p.w - 2.0f * fmaf(qx, p.x, fmaf(qy, p.y, qz * p.z));
            if (gbase + lane == q) d = 3.0e38f;

            unsigned m = __ballot_sync(0xffffffffu, d < cm);
            while (m) {
                const int src = __ffs(m) - 1; m &= m - 1;
                const float dd = __shfl_sync(0xffffffffu, d, src);
                const int   ii = gbase + src;
                const unsigned less = __ballot_sync(0xffffffffu,
                        (v < dd) || (v == dd && vi < ii));
                const int pos = __popc(less);
                const float pv = __shfl_up_sync(0xffffffffu, v, 1);
                const int   pi = __shfl_up_sync(0xffffffffu, vi, 1);
                if (pos < 32) {
                    if (lane == pos)      { v = dd; vi = ii; }
                    else if (lane > pos)  { v = pv; vi = pi; }
                }
                cm = __shfl_sync(0xffffffffu, v, 31);
            }
        }
    }
    idx[((size_t)b * NPTS + q) * KNB + lane] = vi;
}

// =================================================================
// K2: per-point 3-layer MLP (3->64->64->128), f32x2 packed math.
// =================================================================
#define SMEM_FEAT_FLOATS (192 + 64 + 4096 + 64 + 8192 + 128)
#define SMEM_FEAT_BYTES  (SMEM_FEAT_FLOATS * 4)

__global__ __launch_bounds__(128) void feat_kernel(
    const float* __restrict__ x,
    const float* __restrict__ sW0, const float* __restrict__ sb0,
    const float* __restrict__ sW1, const float* __restrict__ sb1,
    const float* __restrict__ sW2, const float* __restrict__ sb2,
    float* __restrict__ feat, int B)
{
    extern __shared__ float sm[];
    float* w0s = sm;
    float* b0s = w0s + 192;
    float* w1s = b0s + 64;
    float* b1s = w1s + 4096;
    float* w2s = b1s + 64;
    float* b2s = w2s + 8192;

    const int s = blockIdx.y, b = blockIdx.z;
    const int tid = threadIdx.x;

    for (int i = tid; i < 192;  i += 128) w0s[i] = sW0[s * 192 + i];
    for (int i = tid; i < 64;   i += 128) { b0s[i] = sb0[s * 64 + i]; b1s[i] = sb1[s * 64 + i]; }
    for (int i = tid; i < 4096; i += 128) w1s[i] = sW1[s * 4096 + i];
    for (int i = tid; i < 8192; i += 128) w2s[i] = sW2[s * 8192 + i];
    for (int i = tid; i < 128;  i += 128) b2s[i] = sb2[s * 128 + i];
    __syncthreads();

    const int j = blockIdx.x * 128 + tid;
    const float* xb = x + (size_t)b * 3 * NPTS;
    const float px = xb[j], py = xb[NPTS + j], pz = xb[2 * NPTS + j];

    float h0[64];
#pragma unroll
    for (int o = 0; o < 64; o++) {
        float a = fmaf(w0s[o * 3 + 2], pz,
                  fmaf(w0s[o * 3 + 1], py,
                  fmaf(w0s[o * 3 + 0], px, b0s[o])));
        h0[o] = fmaxf(a, 0.0f);
    }

    ull hp[32];
#pragma unroll
    for (int c = 0; c < 32; c++) hp[c] = pack2(h0[2 * c], h0[2 * c + 1]);

    float h1[64];
#pragma unroll
    for (int o = 0; o < 64; o += 2) {
        ull a0 = 0ull, a1 = 0ull;
        const ull* r0 = (const ull*)(w1s + (o    ) * 64);
        const ull* r1 = (const ull*)(w1s + (o + 1) * 64);
#pragma unroll
        for (int c = 0; c < 32; c++) {
            a0 = ffma2(r0[c], hp[c], a0);
            a1 = ffma2(r1[c], hp[c], a1);
        }
        const float2 u0 = unpack2(a0), u1 = unpack2(a1);
        h1[o]     = fmaxf(u0.x + u0.y + b1s[o],     0.0f);
        h1[o + 1] = fmaxf(u1.x + u1.y + b1s[o + 1], 0.0f);
    }

#pragma unroll
    for (int c = 0; c < 32; c++) hp[c] = pack2(h1[2 * c], h1[2 * c + 1]);

    float* fout = feat + ((size_t)(s * B + b) * NPTS + j) * 128;
    for (int o = 0; o < 128; o += 4) {
        ull a0 = 0ull, a1 = 0ull, a2 = 0ull, a3 = 0ull;
        const ull* r0 = (const ull*)(w2s + (size_t)(o    ) * 64);
        const ull* r1 = (const ull*)(w2s + (size_t)(o + 1) * 64);
        const ull* r2 = (const ull*)(w2s + (size_t)(o + 2) * 64);
        const ull* r3 = (const ull*)(w2s + (size_t)(o + 3) * 64);
#pragma unroll
        for (int c = 0; c < 32; c++) {
            a0 = ffma2(r0[c], hp[c], a0);
            a1 = ffma2(r1[c], hp[c], a1);
            a2 = ffma2(r2[c], hp[c], a2);
            a3 = ffma2(r3[c], hp[c], a3);
        }
        const float2 u0 = unpack2(a0), u1 = unpack2(a1);
        const float2 u2 = unpack2(a2), u3 = unpack2(a3);
        float4 o4;
        o4.x = fmaxf(u0.x + u0.y + b2s[o],     0.0f);
        o4.y = fmaxf(u1.x + u1.y + b2s[o + 1], 0.0f);
        o4.z = fmaxf(u2.x + u2.y + b2s[o + 2], 0.0f);
        o4.w = fmaxf(u3.x + u3.y + b2s[o + 3], 0.0f);
        *(float4*)(fout + o) = o4;
    }
}

// =================================================================
// K3: gather-max over 32 neighbors -> point_t[b][n][384]
// =================================================================
__global__ __launch_bounds__(256) void maxpool_kernel(
    const float* __restrict__ feat, const int* __restrict__ idx,
    float* __restrict__ point_t, int B)
{
    const int s = blockIdx.y, b = blockIdx.z;
    const int tid = threadIdx.x;
    const int w = tid >> 5, lane = tid & 31;
    const int n = blockIdx.x * 8 + w;

    const int ki = idx[((size_t)b * NPTS + n) * KNB + lane];
    const float* fb = feat + (size_t)(s * B + b) * NPTS * 128;

    float4 m = make_float4(-3.0e38f, -3.0e38f, -3.0e38f, -3.0e38f);
#pragma unroll
    for (int k = 0; k < KNB; k++) {
        const int j = __shfl_sync(0xffffffffu, ki, k);
        const float4 vv = *(const float4*)(fb + (size_t)j * 128 + lane * 4);
        m.x = fmaxf(m.x, vv.x); m.y = fmaxf(m.y, vv.y);
        m.z = fmaxf(m.z, vv.z); m.w = fmaxf(m.w, vv.w);
    }
    *(float4*)(point_t + ((size_t)b * NPTS + n) * 384 + s * 128 + lane * 4) = m;
}

// =================================================================
// K4: mma.sync tf32 GEMM, 3xTF32 split, ldmatrix fragments,
// double-buffered smem. CTA 128x128, 8 warps (2M x 4N), k-chunk 16.
// smem rows = [dim][k] row-major, pitch 20 words (80 B, LDSM
// conflict-free). Y_t[b][n][m] = relu(W @ X_t^T + bias).
// =================================================================
#define KCH   16
#define PITCH 20                       // words per row (16 used + 4 pad)
#define TILE_WORDS (128 * PITCH)       // 2560 words per (buf,split) tile
#define SMEM_GEMM_BYTES (8 * TILE_WORDS * 4)   // A(4) + B(4) tiles = 81920

__global__ __launch_bounds__(256) void gemm_mma(
    const float* __restrict__ W, const float* __restrict__ bias,
    const float* __restrict__ X, float* __restrict__ Y, int M, int K)
{
    extern __shared__ __align__(16) float smem[];
    const uint32_t sb = smem_u32(smem);

    const int tid = threadIdx.x, wid = tid >> 5, lane = tid & 31;
    const int wm = wid & 1, wn = wid >> 1;           // 2 x 4 warp grid
    const int m0 = blockIdx.x * 128, n0 = blockIdx.y * 128;
    const int bi = blockIdx.z;
    const float* Xb = X + (size_t)bi * NPTS * K;

    // loader coords: row = tid>>1 (0..127), k-half = (tid&1)*8
    const int lrow = tid >> 1;
    const int lkq  = (tid & 1) << 3;
    float* sA = smem;                     // [buf][split] tiles
    float* sB = smem + 4 * TILE_WORDS;

    // ldmatrix base addresses (bytes)
    const uint32_t aBase = sb + ((uint32_t)(wm * 64 + (lane & 15)) * PITCH) * 4
                              + ((lane & 16) ? 16 : 0);
    const uint32_t bBase = sb + 4u * TILE_WORDS * 4
                              + ((uint32_t)(wn * 32 + (lane & 7) + ((lane & 16) ? 8 : 0)) * PITCH) * 4
                              + ((lane & 8) ? 16 : 0);

    float acc[4][4][4];
#pragma unroll
    for (int i = 0; i < 4; i++)
#pragma unroll
        for (int j = 0; j < 4; j++)
#pragma unroll
            for (int r = 0; r < 4; r++) acc[i][j][r] = 0.0f;

    const int nch = K / KCH;

    float4 pa0, pa1, pb0, pb1;
    {
        const float* wp = W + (size_t)(m0 + lrow) * K + lkq;
        const float* xp = Xb + (size_t)(n0 + lrow) * K + lkq;
        pa0 = *(const float4*)(wp); pa1 = *(const float4*)(wp + 4);
        pb0 = *(const float4*)(xp); pb1 = *(const float4*)(xp + 4);
    }
    // split + store chunk 0 into buffer 0
    {
        const float a[8] = {pa0.x, pa0.y, pa0.z, pa0.w, pa1.x, pa1.y, pa1.z, pa1.w};
        const float b[8] = {pb0.x, pb0.y, pb0.z, pb0.w, pb1.x, pb1.y, pb1.z, pb1.w};
        uint32_t ah[8], al[8], bh[8], bl[8];
#pragma unroll
        for (int j = 0; j < 8; j++) { split_tf32(a[j], ah[j], al[j]); split_tf32(b[j], bh[j], bl[j]); }
        const int ro = lrow * PITCH + lkq;
#pragma unroll
        for (int q = 0; q < 2; q++) {
            *(uint4*)(sA + 0 * TILE_WORDS + ro + q * 4) = *(uint4*)(ah + q * 4);
            *(uint4*)(sA + 1 * TILE_WORDS + ro + q * 4) = *(uint4*)(al + q * 4);
            *(uint4*)(sB + 0 * TILE_WORDS + ro + q * 4) = *(uint4*)(bh + q * 4);
            *(uint4*)(sB + 1 * TILE_WORDS + ro + q * 4) = *(uint4*)(bl + q * 4);
        }
    }
    __syncthreads();

    for (int ch = 0; ch < nch; ch++) {
        const int cur = ch & 1, nxt = cur ^ 1;
        const bool more = (ch + 1 < nch);

        if (more) {
            const int k0 = (ch + 1) * KCH;
            const float* wp = W + (size_t)(m0 + lrow) * K + k0 + lkq;
            const float* xp = Xb + (size_t)(n0 + lrow) * K + k0 + lkq;
            pa0 = *(const float4*)(wp); pa1 = *(const float4*)(wp + 4);
            pb0 = *(const float4*)(xp); pb1 = *(const float4*)(xp + 4);
        }

        const uint32_t aCur = aBase + (uint32_t)(cur * 2) * TILE_WORDS * 4;
        const uint32_t bCur = bBase + (uint32_t)(cur * 2) * TILE_WORDS * 4;
#pragma unroll
        for (int ks = 0; ks < 2; ks++) {
            uint32_t ah[4][4], al[4][4], bh[4][2], bl[4][2];
#pragma unroll
            for (int mi = 0; mi < 4; mi++) {
                const uint32_t ao = aCur + (uint32_t)mi * (16 * PITCH * 4) + ks * 32;
                ldsm4(ah[mi][0], ah[mi][1], ah[mi][2], ah[mi][3], ao);
                ldsm4(al[mi][0], al[mi][1], al[mi][2], al[mi][3], ao + TILE_WORDS * 4);
            }
#pragma unroll
            for (int pr = 0; pr < 2; pr++) {
                const uint32_t bo = bCur + (uint32_t)pr * (16 * PITCH * 4) + ks * 32;
                ldsm4(bh[pr * 2][0], bh[pr * 2][1], bh[pr * 2 + 1][0], bh[pr * 2 + 1][1], bo);
                ldsm4(bl[pr * 2][0], bl[pr * 2][1], bl[pr * 2 + 1][0], bl[pr * 2 + 1][1],
                      bo + TILE_WORDS * 4);
            }
#pragma unroll
            for (int mi = 0; mi < 4; mi++)
#pragma unroll
                for (int ni = 0; ni < 4; ni++) {
                    mma_tf32(acc[mi][ni], ah[mi], bh[ni]);
                    mma_tf32(acc[mi][ni], ah[mi], bl[ni]);
                    mma_tf32(acc[mi][ni], al[mi], bh[ni]);
                }
        }

        if (more) {
            const float a[8] = {pa0.x, pa0.y, pa0.z, pa0.w, pa1.x, pa1.y, pa1.z, pa1.w};
            const float b[8] = {pb0.x, pb0.y, pb0.z, pb0.w, pb1.x, pb1.y, pb1.z, pb1.w};
            uint32_t ah[8], al[8], bh[8], bl[8];
#pragma unroll
            for (int j = 0; j < 8; j++) { split_tf32(a[j], ah[j], al[j]); split_tf32(b[j], bh[j], bl[j]); }
            const int ro = lrow * PITCH + lkq;
            float* sAn = sA + nxt * 2 * TILE_WORDS;
            float* sBn = sB + nxt * 2 * TILE_WORDS;
#pragma unroll
            for (int q = 0; q < 2; q++) {
                *(uint4*)(sAn + 0 * TILE_WORDS + ro + q * 4) = *(uint4*)(ah + q * 4);
                *(uint4*)(sAn + 1 * TILE_WORDS + ro + q * 4) = *(uint4*)(al + q * 4);
                *(uint4*)(sBn + 0 * TILE_WORDS + ro + q * 4) = *(uint4*)(bh + q * 4);
                *(uint4*)(sBn + 1 * TILE_WORDS + ro + q * 4) = *(uint4*)(bl + q * 4);
            }
        }
        __syncthreads();
    }

    // epilogue: c0:(g, 2t) c1:(g, 2t+1) c2:(g+8, 2t) c3:(g+8, 2t+1)
    const int g = lane >> 2, t2 = (lane & 3) * 2;
#pragma unroll
    for (int mi = 0; mi < 4; mi++) {
        const int mlo = m0 + wm * 64 + mi * 16 + g;
        const float bv0 = bias[mlo], bv1 = bias[mlo + 8];
#pragma unroll
        for (int ni = 0; ni < 4; ni++) {
            const int n = n0 + wn * 32 + ni * 8 + t2;
            float* y0 = Y + ((size_t)bi * NPTS + n) * M;
            float* y1 = y0 + M;
            y0[mlo]     = fmaxf(acc[mi][ni][0] + bv0, 0.0f);
            y1[mlo]     = fmaxf(acc[mi][ni][1] + bv0, 0.0f);
            y0[mlo + 8] = fmaxf(acc[mi][ni][2] + bv1, 0.0f);
            y1[mlo + 8] = fmaxf(acc[mi][ni][3] + bv1, 0.0f);
        }
    }
}

// =================================================================
// rowmax over n for gf_t[b][n][1024] -> out[b][1024]
// =================================================================
__global__ __launch_bounds__(256) void rowmax_t_kernel(const float* __restrict__ gf,
                                                       float* __restrict__ out)
{
    const int c = blockIdx.x * 256 + threadIdx.x;
    const int b = blockIdx.y;
    const float* p = gf + (size_t)b * NPTS * 1024 + c;
    float m0 = -3.0e38f, m1 = -3.0e38f, m2 = -3.0e38f, m3 = -3.0e38f;
    float m4 = -3.0e38f, m5 = -3.0e38f, m6 = -3.0e38f, m7 = -3.0e38f;
    for (int n = 0; n < NPTS; n += 8) {
        m0 = fmaxf(m0, p[(size_t)(n    ) * 1024]);
        m1 = fmaxf(m1, p[(size_t)(n + 1) * 1024]);
        m2 = fmaxf(m2, p[(size_t)(n + 2) * 1024]);
        m3 = fmaxf(m3, p[(size_t)(n + 3) * 1024]);
        m4 = fmaxf(m4, p[(size_t)(n + 4) * 1024]);
        m5 = fmaxf(m5, p[(size_t)(n + 5) * 1024]);
        m6 = fmaxf(m6, p[(size_t)(n + 6) * 1024]);
        m7 = fmaxf(m7, p[(size_t)(n + 7) * 1024]);
    }
    m0 = fmaxf(fmaxf(m0, m1), fmaxf(m2, m3));
    m4 = fmaxf(fmaxf(m4, m5), fmaxf(m6, m7));
    out[(size_t)b * 1024 + c] = fmaxf(m0, m4);
}

// =================================================================
// transpose msf_t[b][n][128] -> out[b][128][n]
// =================================================================
__global__ void transpose_msf(const float* __restrict__ in, float* __restrict__ out)
{
    __shared__ float t[32][33];
    const int b = blockIdx.z;
    const int n0 = blockIdx.x * 32, c0 = blockIdx.y * 32;
    const int tx = threadIdx.x, ty = threadIdx.y;   // 32 x 8
#pragma unroll
    for (int r = 0; r < 32; r += 8)
        t[ty + r][tx] = in[(size_t)((size_t)b * NPTS + n0 + ty + r) * 128 + c0 + tx];
    __syncthreads();
#pragma unroll
    for (int r = 0; r < 32; r += 8)
        out[(size_t)((size_t)b * 128 + c0 + ty + r) * NPTS + n0 + tx] = t[tx][ty + r];
}

// =================================================================
extern "C" void kernel_launch(void* const* d_in, const int* in_sizes, int n_in,
                              void* d_out, int out_size)
{
    const float* x   = (const float*)d_in[0];
    const float* sW0 = (const float*)d_in[1];
    const float* sb0 = (const float*)d_in[2];
    const float* sW1 = (const float*)d_in[3];
    const float* sb1 = (const float*)d_in[4];
    const float* sW2 = (const float*)d_in[5];
    const float* sb2 = (const float*)d_in[6];
    const float* gW0 = (const float*)d_in[7];
    const float* gb0 = (const float*)d_in[8];
    const float* gW1 = (const float*)d_in[9];
    const float* gb1 = (const float*)d_in[10];
    const float* mW0 = (const float*)d_in[11];
    const float* mb0 = (const float*)d_in[12];
    const float* mW1 = (const float*)d_in[13];
    const float* mb1 = (const float*)d_in[14];

    const int B = in_sizes[0] / (3 * NPTS);
    float* out = (float*)d_out;

    void *p_idx, *p_feat, *p_point, *p_gf0, *p_gf, *p_msf0, *p_msf;
    cudaGetSymbolAddress(&p_idx,   g_idx);
    cudaGetSymbolAddress(&p_feat,  g_feat);
    cudaGetSymbolAddress(&p_point, g_point_t);
    cudaGetSymbolAddress(&p_gf0,   g_gf0_t);
    cudaGetSymbolAddress(&p_gf,    g_gf_t);
    cudaGetSymbolAddress(&p_msf0,  g_msf0_t);
    cudaGetSymbolAddress(&p_msf,   g_msf_t);

    cudaFuncSetAttribute(feat_kernel,
                         cudaFuncAttributeMaxDynamicSharedMemorySize, SMEM_FEAT_BYTES);
    cudaFuncSetAttribute(gemm_mma,
                         cudaFuncAttributeMaxDynamicSharedMemorySize, SMEM_GEMM_BYTES);

    // 1) KNN
    knn_kernel<<<dim3(NPTS / 8, B), 256>>>(x, (int*)p_idx);

    // 2) per-point MLP features
    feat_kernel<<<dim3(NPTS / 128, 3, B), 128, SMEM_FEAT_BYTES>>>(
        x, sW0, sb0, sW1, sb1, sW2, sb2, (float*)p_feat, B);

    // 3) gather-max -> point_t[b][n][384]
    maxpool_kernel<<<dim3(NPTS / 8, 3, B), 256>>>(
        (const float*)p_feat, (const int*)p_idx, (float*)p_point, B);

    // 4) gf0_t[b][n][256] = relu(gW0 @ point)   M=256,K=384
    gemm_mma<<<dim3(256 / 128, NPTS / 128, B), 256, SMEM_GEMM_BYTES>>>(
        gW0, gb0, (const float*)p_point, (float*)p_gf0, 256, 384);

    // 5) gf_t[b][n][1024] = relu(gW1 @ gf0)     M=1024,K=256
    gemm_mma<<<dim3(1024 / 128, NPTS / 128, B), 256, SMEM_GEMM_BYTES>>>(
        gW1, gb1, (const float*)p_gf0, (float*)p_gf, 1024, 256);

    // 6) global_feature -> d_out[0 : B*1024]
    rowmax_t_kernel<<<dim3(1024 / 256, B), 256>>>((const float*)p_gf, out);

    // 7) msf0_t[b][n][256] = relu(mW0 @ gf)     M=256,K=1024
    gemm_mma<<<dim3(256 / 128, NPTS / 128, B), 256, SMEM_GEMM_BYTES>>>(
        mW0, mb0, (const float*)p_gf, (float*)p_msf0, 256, 1024);

    // 8) msf_t[b][n][128] = relu(mW1 @ msf0)    M=128,K=256
    gemm_mma<<<dim3(128 / 128, NPTS / 128, B), 256, SMEM_GEMM_BYTES>>>(
        mW1, mb1, (const float*)p_msf0, (float*)p_msf, 128, 256);

    // 9) transpose -> d_out[B*1024 : ] as [B,128,N]
    transpose_msf<<<dim3(NPTS / 32, 128 / 32, B), dim3(32, 8)>>>(
        (const float*)p_msf, out + (size_t)B * 1024);
}

// round 10
// speedup vs baseline: 1.5757x; 1.3107x over previous
#include <cuda_runtime.h>
#include <cuda_bf16.h>
#include <cstdint>

#define NPTS 4096
#define KNB  32
#define BMAX 4

typedef unsigned long long ull;

// ---------------- f32x2 helpers (feat kernel) ----------------
__device__ __forceinline__ ull pack2(float lo, float hi) {
    ull r; asm("mov.b64 %0, {%1, %2};" : "=l"(r) : "f"(lo), "f"(hi)); return r;
}
__device__ __forceinline__ ull ffma2(ull a, ull b, ull c) {
    ull d; asm("fma.rn.f32x2 %0, %1, %2, %3;" : "=l"(d) : "l"(a), "l"(b), "l"(c));
    return d;
}
__device__ __forceinline__ float2 unpack2(ull v) {
    float lo, hi; asm("mov.b64 {%0, %1}, %2;" : "=f"(lo), "=f"(hi) : "l"(v));
    return make_float2(lo, hi);
}

// ---------------- bf16 split + mma helpers ----------------
// v[8] fp32 -> h[4]/l[4] packed bf16x2 (lo half = even k index)
__device__ __forceinline__ void cvt_split8(const float* v, uint32_t* h, uint32_t* l) {
#pragma unroll
    for (int j = 0; j < 4; j++) {
        uint32_t hh;
        asm("cvt.rn.bf16x2.f32 %0, %1, %2;" : "=r"(hh) : "f"(v[2 * j + 1]), "f"(v[2 * j]));
        const float f0 = __uint_as_float(hh << 16);
        const float f1 = __uint_as_float(hh & 0xFFFF0000u);
        uint32_t ll;
        asm("cvt.rn.bf16x2.f32 %0, %1, %2;" : "=r"(ll)
            : "f"(v[2 * j + 1] - f1), "f"(v[2 * j] - f0));
        h[j] = hh; l[j] = ll;
    }
}
__device__ __forceinline__ void mma_bf16(float* c, const uint32_t* a, const uint32_t* b) {
    asm volatile(
        "mma.sync.aligned.m16n8k16.row.col.f32.bf16.bf16.f32 "
        "{%0,%1,%2,%3}, {%4,%5,%6,%7}, {%8,%9}, {%0,%1,%2,%3};"
        : "+f"(c[0]), "+f"(c[1]), "+f"(c[2]), "+f"(c[3])
        : "r"(a[0]), "r"(a[1]), "r"(a[2]), "r"(a[3]), "r"(b[0]), "r"(b[1]));
}
__device__ __forceinline__ void ldsm4(uint32_t& r0, uint32_t& r1, uint32_t& r2, uint32_t& r3,
                                      uint32_t addr) {
    asm volatile("ldmatrix.sync.aligned.m8n8.x4.shared.b16 {%0,%1,%2,%3}, [%4];"
                 : "=r"(r0), "=r"(r1), "=r"(r2), "=r"(r3) : "r"(addr));
}
__device__ __forceinline__ uint32_t smem_u32(const void* p) {
    uint32_t a;
    asm("{ .reg .u64 t; cvta.to.shared.u64 t, %1; cvt.u32.u64 %0, t; }" : "=r"(a) : "l"(p));
    return a;
}

// ---------------- scratch ----------------
__device__ __align__(16) int   g_idx    [BMAX * NPTS * KNB];
__device__ __align__(16) float g_feat   [(size_t)3 * BMAX * NPTS * 128];
__device__ __align__(16) float g_point_t[(size_t)BMAX * NPTS * 384];
__device__ __align__(16) float g_gf0_t  [(size_t)BMAX * NPTS * 256];
__device__ __align__(16) float g_gf_t   [(size_t)BMAX * NPTS * 1024];
__device__ __align__(16) float g_msf0_t [(size_t)BMAX * NPTS * 256];
__device__ __align__(16) float g_msf_t  [(size_t)BMAX * NPTS * 128];
__device__ __align__(16) float g_part   [BMAX * 16 * 1024];

// =================================================================
// K1: KNN — warp per query, lane-distributed sorted top-32 list
// =================================================================
__global__ __launch_bounds__(256) void knn_kernel(const float* __restrict__ x,
                                                  int* __restrict__ idx)
{
    __shared__ float4 tile[1024];
    const int b = blockIdx.y;
    const int tid = threadIdx.x;
    const int w = tid >> 5, lane = tid & 31;
    const int q = blockIdx.x * 8 + w;
    const float* xb = x + (size_t)b * 3 * NPTS;

    const float qx = xb[q], qy = xb[NPTS + q], qz = xb[2 * NPTS + q];
    const float qsq = qx * qx + qy * qy + qz * qz;

    float v = 3.0e38f;
    int   vi = 0x7fffffff;
    float cm = 3.0e38f;

    for (int t0 = 0; t0 < NPTS; t0 += 1024) {
        __syncthreads();
        for (int i = tid; i < 1024; i += 256) {
            const int g = t0 + i;
            const float cx = xb[g], cy = xb[NPTS + g], cz = xb[2 * NPTS + g];
            tile[i] = make_float4(cx, cy, cz, cx * cx + cy * cy + cz * cz);
        }
        __syncthreads();

        for (int c = 0; c < 32; c++) {
            const int gbase = t0 + c * 32;
            const float4 p = tile[c * 32 + lane];
            float d = qsq + p.w - 2.0f * fmaf(qx, p.x, fmaf(qy, p.y, qz * p.z));
            if (gbase + lane == q) d = 3.0e38f;

            unsigned m = __ballot_sync(0xffffffffu, d < cm);
            while (m) {
                const int src = __ffs(m) - 1; m &= m - 1;
                const float dd = __shfl_sync(0xffffffffu, d, src);
                const int   ii = gbase + src;
                const unsigned less = __ballot_sync(0xffffffffu,
                        (v < dd) || (v == dd && vi < ii));
                const int pos = __popc(less);
                const float pv = __shfl_up_sync(0xffffffffu, v, 1);
                const int   pi = __shfl_up_sync(0xffffffffu, vi, 1);
                if (pos < 32) {
                    if (lane == pos)      { v = dd; vi = ii; }
                    else if (lane > pos)  { v = pv; vi = pi; }
                }
                cm = __shfl_sync(0xffffffffu, v, 31);
            }
        }
    }
    idx[((size_t)b * NPTS + q) * KNB + lane] = vi;
}

// =================================================================
// K2: per-point 3-layer MLP (3->64->64->128), f32x2 packed math.
// =================================================================
#define SMEM_FEAT_FLOATS (192 + 64 + 4096 + 64 + 8192 + 128)
#define SMEM_FEAT_BYTES  (SMEM_FEAT_FLOATS * 4)

__global__ __launch_bounds__(128) void feat_kernel(
    const float* __restrict__ x,
    const float* __restrict__ sW0, const float* __restrict__ sb0,
    const float* __restrict__ sW1, const float* __restrict__ sb1,
    const float* __restrict__ sW2, const float* __restrict__ sb2,
    float* __restrict__ feat, int B)
{
    extern __shared__ float sm[];
    float* w0s = sm;
    float* b0s = w0s + 192;
    float* w1s = b0s + 64;
    float* b1s = w1s + 4096;
    float* w2s = b1s + 64;
    float* b2s = w2s + 8192;

    const int s = blockIdx.y, b = blockIdx.z;
    const int tid = threadIdx.x;

    for (int i = tid; i < 192;  i += 128) w0s[i] = sW0[s * 192 + i];
    for (int i = tid; i < 64;   i += 128) { b0s[i] = sb0[s * 64 + i]; b1s[i] = sb1[s * 64 + i]; }
    for (int i = tid; i < 4096; i += 128) w1s[i] = sW1[s * 4096 + i];
    for (int i = tid; i < 8192; i += 128) w2s[i] = sW2[s * 8192 + i];
    for (int i = tid; i < 128;  i += 128) b2s[i] = sb2[s * 128 + i];
    __syncthreads();

    const int j = blockIdx.x * 128 + tid;
    const float* xb = x + (size_t)b * 3 * NPTS;
    const float px = xb[j], py = xb[NPTS + j], pz = xb[2 * NPTS + j];

    float h0[64];
#pragma unroll
    for (int o = 0; o < 64; o++) {
        float a = fmaf(w0s[o * 3 + 2], pz,
                  fmaf(w0s[o * 3 + 1], py,
                  fmaf(w0s[o * 3 + 0], px, b0s[o])));
        h0[o] = fmaxf(a, 0.0f);
    }

    ull hp[32];
#pragma unroll
    for (int c = 0; c < 32; c++) hp[c] = pack2(h0[2 * c], h0[2 * c + 1]);

    float h1[64];
#pragma unroll
    for (int o = 0; o < 64; o += 2) {
        ull a0 = 0ull, a1 = 0ull;
        const ull* r0 = (const ull*)(w1s + (o    ) * 64);
        const ull* r1 = (const ull*)(w1s + (o + 1) * 64);
#pragma unroll
        for (int c = 0; c < 32; c++) {
            a0 = ffma2(r0[c], hp[c], a0);
            a1 = ffma2(r1[c], hp[c], a1);
        }
        const float2 u0 = unpack2(a0), u1 = unpack2(a1);
        h1[o]     = fmaxf(u0.x + u0.y + b1s[o],     0.0f);
        h1[o + 1] = fmaxf(u1.x + u1.y + b1s[o + 1], 0.0f);
    }

#pragma unroll
    for (int c = 0; c < 32; c++) hp[c] = pack2(h1[2 * c], h1[2 * c + 1]);

    float* fout = feat + ((size_t)(s * B + b) * NPTS + j) * 128;
    for (int o = 0; o < 128; o += 4) {
        ull a0 = 0ull, a1 = 0ull, a2 = 0ull, a3 = 0ull;
        const ull* r0 = (const ull*)(w2s + (size_t)(o    ) * 64);
        const ull* r1 = (const ull*)(w2s + (size_t)(o + 1) * 64);
        const ull* r2 = (const ull*)(w2s + (size_t)(o + 2) * 64);
        const ull* r3 = (const ull*)(w2s + (size_t)(o + 3) * 64);
#pragma unroll
        for (int c = 0; c < 32; c++) {
            a0 = ffma2(r0[c], hp[c], a0);
            a1 = ffma2(r1[c], hp[c], a1);
            a2 = ffma2(r2[c], hp[c], a2);
            a3 = ffma2(r3[c], hp[c], a3);
        }
        const float2 u0 = unpack2(a0), u1 = unpack2(a1);
        const float2 u2 = unpack2(a2), u3 = unpack2(a3);
        float4 o4;
        o4.x = fmaxf(u0.x + u0.y + b2s[o],     0.0f);
        o4.y = fmaxf(u1.x + u1.y + b2s[o + 1], 0.0f);
        o4.z = fmaxf(u2.x + u2.y + b2s[o + 2], 0.0f);
        o4.w = fmaxf(u3.x + u3.y + b2s[o + 3], 0.0f);
        *(float4*)(fout + o) = o4;
    }
}

// =================================================================
// K3: gather-max over 32 neighbors -> point_t[b][n][384]
// =================================================================
__global__ __launch_bounds__(256) void maxpool_kernel(
    const float* __restrict__ feat, const int* __restrict__ idx,
    float* __restrict__ point_t, int B)
{
    const int s = blockIdx.y, b = blockIdx.z;
    const int tid = threadIdx.x;
    const int w = tid >> 5, lane = tid & 31;
    const int n = blockIdx.x * 8 + w;

    const int ki = idx[((size_t)b * NPTS + n) * KNB + lane];
    const float* fb = feat + (size_t)(s * B + b) * NPTS * 128;

    float4 m = make_float4(-3.0e38f, -3.0e38f, -3.0e38f, -3.0e38f);
#pragma unroll
    for (int k = 0; k < KNB; k++) {
        const int j = __shfl_sync(0xffffffffu, ki, k);
        const float4 vv = *(const float4*)(fb + (size_t)j * 128 + lane * 4);
        m.x = fmaxf(m.x, vv.x); m.y = fmaxf(m.y, vv.y);
        m.z = fmaxf(m.z, vv.z); m.w = fmaxf(m.w, vv.w);
    }
    *(float4*)(point_t + ((size_t)b * NPTS + n) * 384 + s * 128 + lane * 4) = m;
}

// =================================================================
// K4: mma.sync bf16 GEMM (2-way split, 3 products ~ fp32-accurate).
// Y_t[b][n][m] = relu( W[M,K] @ X_t[b][n][K]^T + bias )
// CTA 128(M) x 64(N), 8 warps (2M x 4N, warp tile 64x16), k-chunk 32.
// smem: bf16 rows [dim][k], pitch 80 B (64 data + 16 pad), LDSM
// conflict-free. Double buffered. 2 CTAs/SM.
// =================================================================
#define KCH    32                      // k elements per chunk
#define APITCH 80                      // bytes per row
#define ATILE  (128 * APITCH)          // 10240 B per (buf,split) A tile
#define BTILE  (64 * APITCH)           // 5120 B per (buf,split) B tile
#define BBASE  (4 * ATILE)
#define SMEM_GEMM_BYTES (4 * ATILE + 4 * BTILE)   // 61440

__global__ __launch_bounds__(256, 2) void gemm_mma(
    const float* __restrict__ W, const float* __restrict__ bias,
    const float* __restrict__ X, float* __restrict__ Y, int M, int K)
{
    extern __shared__ __align__(16) char smem[];
    const uint32_t sb = smem_u32(smem);

    const int tid = threadIdx.x, wid = tid >> 5, lane = tid & 31;
    const int wm = wid & 1, wn = wid >> 1;           // 2 x 4 warp grid
    const int m0 = blockIdx.x * 128, n0 = blockIdx.y * 64;
    const int bi = blockIdx.z;
    const float* Xb = X + (size_t)bi * NPTS * K;

    // loader coords
    const int arow = tid >> 1, akh = (tid & 1) << 4;     // A: 16 floats
    const int brow = tid & 63, bkq = (tid >> 6) << 3;    // B: 8 floats

    // ldmatrix per-lane byte offsets within a tile
    const uint32_t aOff = (uint32_t)(wm * 64 + (lane & 7) + ((lane >> 3) & 1) * 8) * APITCH
                        + ((lane >> 4) & 1) * 16;
    const uint32_t bOff = (uint32_t)(wn * 16 + (lane & 7) + ((lane >> 4) & 1) * 8) * APITCH
                        + ((lane >> 3) & 1) * 16;

    float acc[4][2][4];
#pragma unroll
    for (int i = 0; i < 4; i++)
#pragma unroll
        for (int j = 0; j < 2; j++)
#pragma unroll
            for (int r = 0; r < 4; r++) acc[i][j][r] = 0.0f;

    const int nch = K / KCH;

    float va[16], vb[8];
    {
        const float* wp = W + (size_t)(m0 + arow) * K + akh;
        const float* xp = Xb + (size_t)(n0 + brow) * K + bkq;
#pragma unroll
        for (int q = 0; q < 4; q++) *(float4*)(va + 4 * q) = *(const float4*)(wp + 4 * q);
        *(float4*)(vb) = *(const float4*)(xp); *(float4*)(vb + 4) = *(const float4*)(xp + 4);
    }
    // convert + store chunk 0 -> buf 0
    {
        uint32_t h[4], l[4];
        const uint32_t aro = (uint32_t)arow * APITCH + akh * 2;
        cvt_split8(va, h, l);
        *(uint4*)(smem + 0 * ATILE + aro) = *(uint4*)h;
        *(uint4*)(smem + 1 * ATILE + aro) = *(uint4*)l;
        cvt_split8(va + 8, h, l);
        *(uint4*)(smem + 0 * ATILE + aro + 16) = *(uint4*)h;
        *(uint4*)(smem + 1 * ATILE + aro + 16) = *(uint4*)l;
        const uint32_t bro = (uint32_t)brow * APITCH + bkq * 2;
        cvt_split8(vb, h, l);
        *(uint4*)(smem + BBASE + 0 * BTILE + bro) = *(uint4*)h;
        *(uint4*)(smem + BBASE + 1 * BTILE + bro) = *(uint4*)l;
    }
    __syncthreads();

    for (int ch = 0; ch < nch; ch++) {
        const int cur = ch & 1, nxt = cur ^ 1;
        const bool more = (ch + 1 < nch);

        if (more) {
            const int k0 = (ch + 1) * KCH;
            const float* wp = W + (size_t)(m0 + arow) * K + k0 + akh;
            const float* xp = Xb + (size_t)(n0 + brow) * K + k0 + bkq;
#pragma unroll
            for (int q = 0; q < 4; q++) *(float4*)(va + 4 * q) = *(const float4*)(wp + 4 * q);
            *(float4*)(vb) = *(const float4*)(xp); *(float4*)(vb + 4) = *(const float4*)(xp + 4);
        }

        const uint32_t aCur = sb + (uint32_t)(cur * 2) * ATILE + aOff;
        const uint32_t bCur = sb + BBASE + (uint32_t)(cur * 2) * BTILE + bOff;
#pragma unroll
        for (int ks = 0; ks < 2; ks++) {
            const uint32_t kso = ks * 32;
            uint32_t bh[2][2], bl[2][2];
            ldsm4(bh[0][0], bh[0][1], bh[1][0], bh[1][1], bCur + kso);
            ldsm4(bl[0][0], bl[0][1], bl[1][0], bl[1][1], bCur + BTILE + kso);
#pragma unroll
            for (int mih = 0; mih < 2; mih++) {
                uint32_t ah[2][4], al[2][4];
#pragma unroll
                for (int mi2 = 0; mi2 < 2; mi2++) {
                    const uint32_t ao = aCur + (uint32_t)(mih * 2 + mi2) * (16 * APITCH) + kso;
                    ldsm4(ah[mi2][0], ah[mi2][1], ah[mi2][2], ah[mi2][3], ao);
                    ldsm4(al[mi2][0], al[mi2][1], al[mi2][2], al[mi2][3], ao + ATILE);
                }
#pragma unroll
                for (int mi2 = 0; mi2 < 2; mi2++)
#pragma unroll
                    for (int ni = 0; ni < 2; ni++) {
                        float* c = acc[mih * 2 + mi2][ni];
                        mma_bf16(c, ah[mi2], bh[ni]);
                        mma_bf16(c, ah[mi2], bl[ni]);
                        mma_bf16(c, al[mi2], bh[ni]);
                    }
            }
        }

        if (more) {
            uint32_t h[4], l[4];
            const uint32_t aro = (uint32_t)arow * APITCH + akh * 2;
            char* sA = smem + (size_t)(nxt * 2) * ATILE;
            char* sB = smem + BBASE + (size_t)(nxt * 2) * BTILE;
            cvt_split8(va, h, l);
            *(uint4*)(sA + aro) = *(uint4*)h;
            *(uint4*)(sA + ATILE + aro) = *(uint4*)l;
            cvt_split8(va + 8, h, l);
            *(uint4*)(sA + aro + 16) = *(uint4*)h;
            *(uint4*)(sA + ATILE + aro + 16) = *(uint4*)l;
            const uint32_t bro = (uint32_t)brow * APITCH + bkq * 2;
            cvt_split8(vb, h, l);
            *(uint4*)(sB + bro) = *(uint4*)h;
            *(uint4*)(sB + BTILE + bro) = *(uint4*)l;
        }
        __syncthreads();
    }

    // epilogue: c0:(g, 2t) c1:(g, 2t+1) c2:(g+8, 2t) c3:(g+8, 2t+1)
    const int g = lane >> 2, t2 = (lane & 3) * 2;
#pragma unroll
    for (int mi = 0; mi < 4; mi++) {
        const int mlo = m0 + wm * 64 + mi * 16 + g;
        const float bv0 = bias[mlo], bv1 = bias[mlo + 8];
#pragma unroll
        for (int ni = 0; ni < 2; ni++) {
            const int n = n0 + wn * 16 + ni * 8 + t2;
            float* y0 = Y + ((size_t)bi * NPTS + n) * M;
            float* y1 = y0 + M;
            y0[mlo]     = fmaxf(acc[mi][ni][0] + bv0, 0.0f);
            y1[mlo]     = fmaxf(acc[mi][ni][1] + bv0, 0.0f);
            y0[mlo + 8] = fmaxf(acc[mi][ni][2] + bv1, 0.0f);
            y1[mlo + 8] = fmaxf(acc[mi][ni][3] + bv1, 0.0f);
        }
    }
}

// =================================================================
// rowmax, two-phase: partial over 256-point slices, then reduce
// =================================================================
__global__ __launch_bounds__(256) void rowmax_part(const float* __restrict__ gf,
                                                   float* __restrict__ part)
{
    const int c = blockIdx.x * 256 + threadIdx.x;
    const int ns = blockIdx.y, b = blockIdx.z;
    const float* p = gf + ((size_t)b * NPTS + ns * 256) * 1024 + c;
    float m0 = -3.0e38f, m1 = -3.0e38f, m2 = -3.0e38f, m3 = -3.0e38f;
#pragma unroll 4
    for (int n = 0; n < 256; n += 4) {
        m0 = fmaxf(m0, p[(size_t)(n    ) * 1024]);
        m1 = fmaxf(m1, p[(size_t)(n + 1) * 1024]);
        m2 = fmaxf(m2, p[(size_t)(n + 2) * 1024]);
        m3 = fmaxf(m3, p[(size_t)(n + 3) * 1024]);
    }
    part[(size_t)(b * 16 + ns) * 1024 + c] = fmaxf(fmaxf(m0, m1), fmaxf(m2, m3));
}

__global__ __launch_bounds__(256) void rowmax_fin(const float* __restrict__ part,
                                                  float* __restrict__ out)
{
    const int c = blockIdx.x * 256 + threadIdx.x;
    const int b = blockIdx.y;
    float m = -3.0e38f;
#pragma unroll
    for (int i = 0; i < 16; i++)
        m = fmaxf(m, part[(size_t)(b * 16 + i) * 1024 + c]);
    out[(size_t)b * 1024 + c] = m;
}

// =================================================================
// transpose msf_t[b][n][128] -> out[b][128][n]
// =================================================================
__global__ void transpose_msf(const float* __restrict__ in, float* __restrict__ out)
{
    __shared__ float t[32][33];
    const int b = blockIdx.z;
    const int n0 = blockIdx.x * 32, c0 = blockIdx.y * 32;
    const int tx = threadIdx.x, ty = threadIdx.y;   // 32 x 8
#pragma unroll
    for (int r = 0; r < 32; r += 8)
        t[ty + r][tx] = in[(size_t)((size_t)b * NPTS + n0 + ty + r) * 128 + c0 + tx];
    __syncthreads();
#pragma unroll
    for (int r = 0; r < 32; r += 8)
        out[(size_t)((size_t)b * 128 + c0 + ty + r) * NPTS + n0 + tx] = t[tx][ty + r];
}

// =================================================================
extern "C" void kernel_launch(void* const* d_in, const int* in_sizes, int n_in,
                              void* d_out, int out_size)
{
    const float* x   = (const float*)d_in[0];
    const float* sW0 = (const float*)d_in[1];
    const float* sb0 = (const float*)d_in[2];
    const float* sW1 = (const float*)d_in[3];
    const float* sb1 = (const float*)d_in[4];
    const float* sW2 = (const float*)d_in[5];
    const float* sb2 = (const float*)d_in[6];
    const float* gW0 = (const float*)d_in[7];
    const float* gb0 = (const float*)d_in[8];
    const float* gW1 = (const float*)d_in[9];
    const float* gb1 = (const float*)d_in[10];
    const float* mW0 = (const float*)d_in[11];
    const float* mb0 = (const float*)d_in[12];
    const float* mW1 = (const float*)d_in[13];
    const float* mb1 = (const float*)d_in[14];

    const int B = in_sizes[0] / (3 * NPTS);
    float* out = (float*)d_out;

    void *p_idx, *p_feat, *p_point, *p_gf0, *p_gf, *p_msf0, *p_msf, *p_part;
    cudaGetSymbolAddress(&p_idx,   g_idx);
    cudaGetSymbolAddress(&p_feat,  g_feat);
    cudaGetSymbolAddress(&p_point, g_point_t);
    cudaGetSymbolAddress(&p_gf0,   g_gf0_t);
    cudaGetSymbolAddress(&p_gf,    g_gf_t);
    cudaGetSymbolAddress(&p_msf0,  g_msf0_t);
    cudaGetSymbolAddress(&p_msf,   g_msf_t);
    cudaGetSymbolAddress(&p_part,  g_part);

    cudaFuncSetAttribute(feat_kernel,
                         cudaFuncAttributeMaxDynamicSharedMemorySize, SMEM_FEAT_BYTES);
    cudaFuncSetAttribute(gemm_mma,
                         cudaFuncAttributeMaxDynamicSharedMemorySize, SMEM_GEMM_BYTES);

    // 1) KNN
    knn_kernel<<<dim3(NPTS / 8, B), 256>>>(x, (int*)p_idx);

    // 2) per-point MLP features
    feat_kernel<<<dim3(NPTS / 128, 3, B), 128, SMEM_FEAT_BYTES>>>(
        x, sW0, sb0, sW1, sb1, sW2, sb2, (float*)p_feat, B);

    // 3) gather-max -> point_t[b][n][384]
    maxpool_kernel<<<dim3(NPTS / 8, 3, B), 256>>>(
        (const float*)p_feat, (const int*)p_idx, (float*)p_point, B);

    // 4) gf0_t[b][n][256] = relu(gW0 @ point)   M=256,K=384
    gemm_mma<<<dim3(256 / 128, NPTS / 64, B), 256, SMEM_GEMM_BYTES>>>(
        gW0, gb0, (const float*)p_point, (float*)p_gf0, 256, 384);

    // 5) gf_t[b][n][1024] = relu(gW1 @ gf0)     M=1024,K=256
    gemm_mma<<<dim3(1024 / 128, NPTS / 64, B), 256, SMEM_GEMM_BYTES>>>(
        gW1, gb1, (const float*)p_gf0, (float*)p_gf, 1024, 256);

    // 6) global_feature -> d_out[0 : B*1024]
    rowmax_part<<<dim3(1024 / 256, 16, B), 256>>>((const float*)p_gf, (float*)p_part);
    rowmax_fin<<<dim3(1024 / 256, B), 256>>>((const float*)p_part, out);

    // 7) msf0_t[b][n][256] = relu(mW0 @ gf)     M=256,K=1024
    gemm_mma<<<dim3(256 / 128, NPTS / 64, B), 256, SMEM_GEMM_BYTES>>>(
        mW0, mb0, (const float*)p_gf, (float*)p_msf0, 256, 1024);

    // 8) msf_t[b][n][128] = relu(mW1 @ msf0)    M=128,K=256
    gemm_mma<<<dim3(128 / 128, NPTS / 64, B), 256, SMEM_GEMM_BYTES>>>(
        mW1, mb1, (const float*)p_msf0, (float*)p_msf, 128, 256);

    // 9) transpose -> d_out[B*1024 : ] as [B,128,N]
    transpose_msf<<<dim3(NPTS / 32, 128 / 32, B), dim3(32, 8)>>>(
        (const float*)p_msf, out + (size_t)B * 1024);
}

// round 11
// speedup vs baseline: 1.9891x; 1.2624x over previous
#include <cuda_runtime.h>
#include <cuda_bf16.h>
#include <cstdint>

#define NPTS 4096
#define KNB  32
#define BMAX 4

typedef unsigned long long ull;

// ---------------- f32x2 helpers (feat kernel) ----------------
__device__ __forceinline__ ull pack2(float lo, float hi) {
    ull r; asm("mov.b64 %0, {%1, %2};" : "=l"(r) : "f"(lo), "f"(hi)); return r;
}
__device__ __forceinline__ ull ffma2(ull a, ull b, ull c) {
    ull d; asm("fma.rn.f32x2 %0, %1, %2, %3;" : "=l"(d) : "l"(a), "l"(b), "l"(c));
    return d;
}
__device__ __forceinline__ float2 unpack2(ull v) {
    float lo, hi; asm("mov.b64 {%0, %1}, %2;" : "=f"(lo), "=f"(hi) : "l"(v));
    return make_float2(lo, hi);
}

// ---------------- bf16 split + mma helpers ----------------
__device__ __forceinline__ void cvt_split8(const float* v, uint32_t* h, uint32_t* l) {
#pragma unroll
    for (int j = 0; j < 4; j++) {
        uint32_t hh;
        asm("cvt.rn.bf16x2.f32 %0, %1, %2;" : "=r"(hh) : "f"(v[2 * j + 1]), "f"(v[2 * j]));
        const float f0 = __uint_as_float(hh << 16);
        const float f1 = __uint_as_float(hh & 0xFFFF0000u);
        uint32_t ll;
        asm("cvt.rn.bf16x2.f32 %0, %1, %2;" : "=r"(ll)
            : "f"(v[2 * j + 1] - f1), "f"(v[2 * j] - f0));
        h[j] = hh; l[j] = ll;
    }
}
__device__ __forceinline__ void mma_bf16(float* c, const uint32_t* a, const uint32_t* b) {
    asm volatile(
        "mma.sync.aligned.m16n8k16.row.col.f32.bf16.bf16.f32 "
        "{%0,%1,%2,%3}, {%4,%5,%6,%7}, {%8,%9}, {%0,%1,%2,%3};"
        : "+f"(c[0]), "+f"(c[1]), "+f"(c[2]), "+f"(c[3])
        : "r"(a[0]), "r"(a[1]), "r"(a[2]), "r"(a[3]), "r"(b[0]), "r"(b[1]));
}
__device__ __forceinline__ void ldsm4(uint32_t& r0, uint32_t& r1, uint32_t& r2, uint32_t& r3,
                                      uint32_t addr) {
    asm volatile("ldmatrix.sync.aligned.m8n8.x4.shared.b16 {%0,%1,%2,%3}, [%4];"
                 : "=r"(r0), "=r"(r1), "=r"(r2), "=r"(r3) : "r"(addr));
}
__device__ __forceinline__ uint32_t smem_u32(const void* p) {
    uint32_t a;
    asm("{ .reg .u64 t; cvta.to.shared.u64 t, %1; cvt.u32.u64 %0, t; }" : "=r"(a) : "l"(p));
    return a;
}

// ---------------- scratch ----------------
__device__ __align__(16) int   g_idx    [BMAX * NPTS * KNB];
__device__ __align__(16) float g_feat   [(size_t)3 * BMAX * NPTS * 128];
__device__ __align__(16) float g_point_t[(size_t)BMAX * NPTS * 384];
__device__ __align__(16) float g_gf0_t  [(size_t)BMAX * NPTS * 256];
__device__ __align__(16) float g_gf_t   [(size_t)BMAX * NPTS * 1024];
__device__ __align__(16) float g_msf0_t [(size_t)BMAX * NPTS * 256];
__device__ __align__(16) float g_msf_t  [(size_t)BMAX * NPTS * 128];
__device__ __align__(16) float g_part   [BMAX * 16 * 1024];

// =================================================================
// K1: KNN — warp per query, lane-distributed sorted top-32 list
// =================================================================
__global__ __launch_bounds__(256) void knn_kernel(const float* __restrict__ x,
                                                  int* __restrict__ idx)
{
    __shared__ float4 tile[1024];
    const int b = blockIdx.y;
    const int tid = threadIdx.x;
    const int w = tid >> 5, lane = tid & 31;
    const int q = blockIdx.x * 8 + w;
    const float* xb = x + (size_t)b * 3 * NPTS;

    const float qx = xb[q], qy = xb[NPTS + q], qz = xb[2 * NPTS + q];
    const float qsq = qx * qx + qy * qy + qz * qz;

    float v = 3.0e38f;
    int   vi = 0x7fffffff;
    float cm = 3.0e38f;

    for (int t0 = 0; t0 < NPTS; t0 += 1024) {
        __syncthreads();
        for (int i = tid; i < 1024; i += 256) {
            const int g = t0 + i;
            const float cx = xb[g], cy = xb[NPTS + g], cz = xb[2 * NPTS + g];
            tile[i] = make_float4(cx, cy, cz, cx * cx + cy * cy + cz * cz);
        }
        __syncthreads();

        for (int c = 0; c < 32; c++) {
            const int gbase = t0 + c * 32;
            const float4 p = tile[c * 32 + lane];
            float d = qsq + p.w - 2.0f * fmaf(qx, p.x, fmaf(qy, p.y, qz * p.z));
            if (gbase + lane == q) d = 3.0e38f;

            unsigned m = __ballot_sync(0xffffffffu, d < cm);
            while (m) {
                const int src = __ffs(m) - 1; m &= m - 1;
                const float dd = __shfl_sync(0xffffffffu, d, src);
                const int   ii = gbase + src;
                const unsigned less = __ballot_sync(0xffffffffu,
                        (v < dd) || (v == dd && vi < ii));
                const int pos = __popc(less);
                const float pv = __shfl_up_sync(0xffffffffu, v, 1);
                const int   pi = __shfl_up_sync(0xffffffffu, vi, 1);
                if (pos < 32) {
                    if (lane == pos)      { v = dd; vi = ii; }
                    else if (lane > pos)  { v = pv; vi = pi; }
                }
                cm = __shfl_sync(0xffffffffu, v, 31);
            }
        }
    }
    idx[((size_t)b * NPTS + q) * KNB + lane] = vi;
}

// =================================================================
// K2: per-point 3-layer MLP (3->64->64->128), f32x2 packed math.
// =================================================================
#define SMEM_FEAT_FLOATS (192 + 64 + 4096 + 64 + 8192 + 128)
#define SMEM_FEAT_BYTES  (SMEM_FEAT_FLOATS * 4)

__global__ __launch_bounds__(128) void feat_kernel(
    const float* __restrict__ x,
    const float* __restrict__ sW0, const float* __restrict__ sb0,
    const float* __restrict__ sW1, const float* __restrict__ sb1,
    const float* __restrict__ sW2, const float* __restrict__ sb2,
    float* __restrict__ feat, int B)
{
    extern __shared__ float sm[];
    float* w0s = sm;
    float* b0s = w0s + 192;
    float* w1s = b0s + 64;
    float* b1s = w1s + 4096;
    float* w2s = b1s + 64;
    float* b2s = w2s + 8192;

    const int s = blockIdx.y, b = blockIdx.z;
    const int tid = threadIdx.x;

    for (int i = tid; i < 192;  i += 128) w0s[i] = sW0[s * 192 + i];
    for (int i = tid; i < 64;   i += 128) { b0s[i] = sb0[s * 64 + i]; b1s[i] = sb1[s * 64 + i]; }
    for (int i = tid; i < 4096; i += 128) w1s[i] = sW1[s * 4096 + i];
    for (int i = tid; i < 8192; i += 128) w2s[i] = sW2[s * 8192 + i];
    for (int i = tid; i < 128;  i += 128) b2s[i] = sb2[s * 128 + i];
    __syncthreads();

    const int j = blockIdx.x * 128 + tid;
    const float* xb = x + (size_t)b * 3 * NPTS;
    const float px = xb[j], py = xb[NPTS + j], pz = xb[2 * NPTS + j];

    float h0[64];
#pragma unroll
    for (int o = 0; o < 64; o++) {
        float a = fmaf(w0s[o * 3 + 2], pz,
                  fmaf(w0s[o * 3 + 1], py,
                  fmaf(w0s[o * 3 + 0], px, b0s[o])));
        h0[o] = fmaxf(a, 0.0f);
    }

    ull hp[32];
#pragma unroll
    for (int c = 0; c < 32; c++) hp[c] = pack2(h0[2 * c], h0[2 * c + 1]);

    float h1[64];
#pragma unroll
    for (int o = 0; o < 64; o += 2) {
        ull a0 = 0ull, a1 = 0ull;
        const ull* r0 = (const ull*)(w1s + (o    ) * 64);
        const ull* r1 = (const ull*)(w1s + (o + 1) * 64);
#pragma unroll
        for (int c = 0; c < 32; c++) {
            a0 = ffma2(r0[c], hp[c], a0);
            a1 = ffma2(r1[c], hp[c], a1);
        }
        const float2 u0 = unpack2(a0), u1 = unpack2(a1);
        h1[o]     = fmaxf(u0.x + u0.y + b1s[o],     0.0f);
        h1[o + 1] = fmaxf(u1.x + u1.y + b1s[o + 1], 0.0f);
    }

#pragma unroll
    for (int c = 0; c < 32; c++) hp[c] = pack2(h1[2 * c], h1[2 * c + 1]);

    float* fout = feat + ((size_t)(s * B + b) * NPTS + j) * 128;
    for (int o = 0; o < 128; o += 4) {
        ull a0 = 0ull, a1 = 0ull, a2 = 0ull, a3 = 0ull;
        const ull* r0 = (const ull*)(w2s + (size_t)(o    ) * 64);
        const ull* r1 = (const ull*)(w2s + (size_t)(o + 1) * 64);
        const ull* r2 = (const ull*)(w2s + (size_t)(o + 2) * 64);
        const ull* r3 = (const ull*)(w2s + (size_t)(o + 3) * 64);
#pragma unroll
        for (int c = 0; c < 32; c++) {
            a0 = ffma2(r0[c], hp[c], a0);
            a1 = ffma2(r1[c], hp[c], a1);
            a2 = ffma2(r2[c], hp[c], a2);
            a3 = ffma2(r3[c], hp[c], a3);
        }
        const float2 u0 = unpack2(a0), u1 = unpack2(a1);
        const float2 u2 = unpack2(a2), u3 = unpack2(a3);
        float4 o4;
        o4.x = fmaxf(u0.x + u0.y + b2s[o],     0.0f);
        o4.y = fmaxf(u1.x + u1.y + b2s[o + 1], 0.0f);
        o4.z = fmaxf(u2.x + u2.y + b2s[o + 2], 0.0f);
        o4.w = fmaxf(u3.x + u3.y + b2s[o + 3], 0.0f);
        *(float4*)(fout + o) = o4;
    }
}

// =================================================================
// K3: gather-max over 32 neighbors -> point_t[b][n][384]
// =================================================================
__global__ __launch_bounds__(256) void maxpool_kernel(
    const float* __restrict__ feat, const int* __restrict__ idx,
    float* __restrict__ point_t, int B)
{
    const int s = blockIdx.y, b = blockIdx.z;
    const int tid = threadIdx.x;
    const int w = tid >> 5, lane = tid & 31;
    const int n = blockIdx.x * 8 + w;

    const int ki = idx[((size_t)b * NPTS + n) * KNB + lane];
    const float* fb = feat + (size_t)(s * B + b) * NPTS * 128;

    float4 m = make_float4(-3.0e38f, -3.0e38f, -3.0e38f, -3.0e38f);
#pragma unroll
    for (int k = 0; k < KNB; k++) {
        const int j = __shfl_sync(0xffffffffu, ki, k);
        const float4 vv = *(const float4*)(fb + (size_t)j * 128 + lane * 4);
        m.x = fmaxf(m.x, vv.x); m.y = fmaxf(m.y, vv.y);
        m.z = fmaxf(m.z, vv.z); m.w = fmaxf(m.w, vv.w);
    }
    *(float4*)(point_t + ((size_t)b * NPTS + n) * 384 + s * 128 + lane * 4) = m;
}

// =================================================================
// K4: mma.sync bf16 GEMM (2-way split, 3 products ~ fp32-accurate).
// Y_t[b][n][m] = relu( W[M,K] @ X_t[b][n][K]^T + bias )
// CTA 128(M) x 128(N), 8 warps = 2M x 4N grid, warp tile 64x32.
// k-chunk 16; smem rows [dim][k] bf16, pitch 48 B (32 data + 16 pad),
// LDSM conflict-free; double buffered; 2 CTAs/SM.
// =================================================================
#define KCH    16
#define PITCH  48                      // bytes per row
#define ATILE  (128 * PITCH)           // 6144 B per (buf,split) tile
#define BTILE  (128 * PITCH)           // 6144 B
#define BBASE  (4 * ATILE)
#define SMEM_GEMM_BYTES (4 * ATILE + 4 * BTILE)   // 49152

__global__ __launch_bounds__(256, 2) void gemm_mma(
    const float* __restrict__ W, const float* __restrict__ bias,
    const float* __restrict__ X, float* __restrict__ Y, int M, int K)
{
    extern __shared__ __align__(16) char smem[];
    const uint32_t sb = smem_u32(smem);

    const int tid = threadIdx.x, wid = tid >> 5, lane = tid & 31;
    const int wm = wid & 1, wn = wid >> 1;           // 2 x 4 warp grid
    const int m0 = blockIdx.x * 128, n0 = blockIdx.y * 128;
    const int bi = blockIdx.z;
    const float* Xb = X + (size_t)bi * NPTS * K;

    // loader coords: row = tid>>1 (0..127), k-quarter = (tid&1)*8 floats
    const int lrow = tid >> 1, lkq = (tid & 1) << 3;

    // ldmatrix per-lane byte offsets within a tile
    const uint32_t aOff = (uint32_t)(wm * 64 + (lane & 7) + ((lane >> 3) & 1) * 8) * PITCH
                        + ((lane >> 4) & 1) * 16;
    const uint32_t bOff = (uint32_t)(wn * 32 + (lane & 7) + ((lane >> 4) & 1) * 8) * PITCH
                        + ((lane >> 3) & 1) * 16;

    float acc[4][4][4];
#pragma unroll
    for (int i = 0; i < 4; i++)
#pragma unroll
        for (int j = 0; j < 4; j++)
#pragma unroll
            for (int r = 0; r < 4; r++) acc[i][j][r] = 0.0f;

    const int nch = K / KCH;

    float va[8], vb[8];
    {
        const float* wp = W + (size_t)(m0 + lrow) * K + lkq;
        const float* xp = Xb + (size_t)(n0 + lrow) * K + lkq;
        *(float4*)(va) = *(const float4*)(wp); *(float4*)(va + 4) = *(const float4*)(wp + 4);
        *(float4*)(vb) = *(const float4*)(xp); *(float4*)(vb + 4) = *(const float4*)(xp + 4);
    }
    // convert + store chunk 0 -> buf 0
    {
        uint32_t h[4], l[4];
        const uint32_t ro = (uint32_t)lrow * PITCH + lkq * 2;
        cvt_split8(va, h, l);
        *(uint4*)(smem + ro)         = *(uint4*)h;
        *(uint4*)(smem + ATILE + ro) = *(uint4*)l;
        cvt_split8(vb, h, l);
        *(uint4*)(smem + BBASE + ro)         = *(uint4*)h;
        *(uint4*)(smem + BBASE + BTILE + ro) = *(uint4*)l;
    }
    __syncthreads();

    for (int ch = 0; ch < nch; ch++) {
        const int cur = ch & 1, nxt = cur ^ 1;
        const bool more = (ch + 1 < nch);

        if (more) {
            const int k0 = (ch + 1) * KCH;
            const float* wp = W + (size_t)(m0 + lrow) * K + k0 + lkq;
            const float* xp = Xb + (size_t)(n0 + lrow) * K + k0 + lkq;
            *(float4*)(va) = *(const float4*)(wp); *(float4*)(va + 4) = *(const float4*)(wp + 4);
            *(float4*)(vb) = *(const float4*)(xp); *(float4*)(vb + 4) = *(const float4*)(xp + 4);
        }

        const uint32_t aCur = sb + (uint32_t)(cur * 2) * ATILE + aOff;
        const uint32_t bCur = sb + BBASE + (uint32_t)(cur * 2) * BTILE + bOff;

        // B fragments for the whole chunk (reused by all 4 mi)
        uint32_t bh[4][2], bl[4][2];
        ldsm4(bh[0][0], bh[0][1], bh[1][0], bh[1][1], bCur);
        ldsm4(bh[2][0], bh[2][1], bh[3][0], bh[3][1], bCur + 16 * PITCH);
        ldsm4(bl[0][0], bl[0][1], bl[1][0], bl[1][1], bCur + BTILE);
        ldsm4(bl[2][0], bl[2][1], bl[3][0], bl[3][1], bCur + BTILE + 16 * PITCH);

#pragma unroll
        for (int mih = 0; mih < 2; mih++) {
            uint32_t ah[2][4], al[2][4];
#pragma unroll
            for (int mi2 = 0; mi2 < 2; mi2++) {
                const uint32_t ao = aCur + (uint32_t)(mih * 2 + mi2) * (16 * PITCH);
                ldsm4(ah[mi2][0], ah[mi2][1], ah[mi2][2], ah[mi2][3], ao);
                ldsm4(al[mi2][0], al[mi2][1], al[mi2][2], al[mi2][3], ao + ATILE);
            }
#pragma unroll
            for (int mi2 = 0; mi2 < 2; mi2++)
#pragma unroll
                for (int ni = 0; ni < 4; ni++) {
                    float* c = acc[mih * 2 + mi2][ni];
                    mma_bf16(c, ah[mi2], bh[ni]);
                    mma_bf16(c, ah[mi2], bl[ni]);
                    mma_bf16(c, al[mi2], bh[ni]);
                }
        }

        if (more) {
            uint32_t h[4], l[4];
            const uint32_t ro = (uint32_t)lrow * PITCH + lkq * 2;
            char* sA = smem + (size_t)(nxt * 2) * ATILE;
            char* sB = smem + BBASE + (size_t)(nxt * 2) * BTILE;
            cvt_split8(va, h, l);
            *(uint4*)(sA + ro)         = *(uint4*)h;
            *(uint4*)(sA + ATILE + ro) = *(uint4*)l;
            cvt_split8(vb, h, l);
            *(uint4*)(sB + ro)         = *(uint4*)h;
            *(uint4*)(sB + BTILE + ro) = *(uint4*)l;
        }
        __syncthreads();
    }

    // epilogue: c0:(g, 2t) c1:(g, 2t+1) c2:(g+8, 2t) c3:(g+8, 2t+1)
    const int g = lane >> 2, t2 = (lane & 3) * 2;
#pragma unroll
    for (int mi = 0; mi < 4; mi++) {
        const int mlo = m0 + wm * 64 + mi * 16 + g;
        const float bv0 = bias[mlo], bv1 = bias[mlo + 8];
#pragma unroll
        for (int ni = 0; ni < 4; ni++) {
            const int n = n0 + wn * 32 + ni * 8 + t2;
            float* y0 = Y + ((size_t)bi * NPTS + n) * M;
            float* y1 = y0 + M;
            y0[mlo]     = fmaxf(acc[mi][ni][0] + bv0, 0.0f);
            y1[mlo]     = fmaxf(acc[mi][ni][1] + bv0, 0.0f);
            y0[mlo + 8] = fmaxf(acc[mi][ni][2] + bv1, 0.0f);
            y1[mlo + 8] = fmaxf(acc[mi][ni][3] + bv1, 0.0f);
        }
    }
}

// =================================================================
// rowmax, two-phase: partial over 256-point slices, then reduce
// =================================================================
__global__ __launch_bounds__(256) void rowmax_part(const float* __restrict__ gf,
                                                   float* __restrict__ part)
{
    const int c = blockIdx.x * 256 + threadIdx.x;
    const int ns = blockIdx.y, b = blockIdx.z;
    const float* p = gf + ((size_t)b * NPTS + ns * 256) * 1024 + c;
    float m0 = -3.0e38f, m1 = -3.0e38f, m2 = -3.0e38f, m3 = -3.0e38f;
#pragma unroll 4
    for (int n = 0; n < 256; n += 4) {
        m0 = fmaxf(m0, p[(size_t)(n    ) * 1024]);
        m1 = fmaxf(m1, p[(size_t)(n + 1) * 1024]);
        m2 = fmaxf(m2, p[(size_t)(n + 2) * 1024]);
        m3 = fmaxf(m3, p[(size_t)(n + 3) * 1024]);
    }
    part[(size_t)(b * 16 + ns) * 1024 + c] = fmaxf(fmaxf(m0, m1), fmaxf(m2, m3));
}

__global__ __launch_bounds__(256) void rowmax_fin(const float* __restrict__ part,
                                                  float* __restrict__ out)
{
    const int c = blockIdx.x * 256 + threadIdx.x;
    const int b = blockIdx.y;
    float m = -3.0e38f;
#pragma unroll
    for (int i = 0; i < 16; i++)
        m = fmaxf(m, part[(size_t)(b * 16 + i) * 1024 + c]);
    out[(size_t)b * 1024 + c] = m;
}

// =================================================================
// transpose msf_t[b][n][128] -> out[b][128][n]
// =================================================================
__global__ void transpose_msf(const float* __restrict__ in, float* __restrict__ out)
{
    __shared__ float t[32][33];
    const int b = blockIdx.z;
    const int n0 = blockIdx.x * 32, c0 = blockIdx.y * 32;
    const int tx = threadIdx.x, ty = threadIdx.y;   // 32 x 8
#pragma unroll
    for (int r = 0; r < 32; r += 8)
        t[ty + r][tx] = in[(size_t)((size_t)b * NPTS + n0 + ty + r) * 128 + c0 + tx];
    __syncthreads();
#pragma unroll
    for (int r = 0; r < 32; r += 8)
        out[(size_t)((size_t)b * 128 + c0 + ty + r) * NPTS + n0 + tx] = t[tx][ty + r];
}

// =================================================================
extern "C" void kernel_launch(void* const* d_in, const int* in_sizes, int n_in,
                              void* d_out, int out_size)
{
    const float* x   = (const float*)d_in[0];
    const float* sW0 = (const float*)d_in[1];
    const float* sb0 = (const float*)d_in[2];
    const float* sW1 = (const float*)d_in[3];
    const float* sb1 = (const float*)d_in[4];
    const float* sW2 = (const float*)d_in[5];
    const float* sb2 = (const float*)d_in[6];
    const float* gW0 = (const float*)d_in[7];
    const float* gb0 = (const float*)d_in[8];
    const float* gW1 = (const float*)d_in[9];
    const float* gb1 = (const float*)d_in[10];
    const float* mW0 = (const float*)d_in[11];
    const float* mb0 = (const float*)d_in[12];
    const float* mW1 = (const float*)d_in[13];
    const float* mb1 = (const float*)d_in[14];

    const int B = in_sizes[0] / (3 * NPTS);
    float* out = (float*)d_out;

    void *p_idx, *p_feat, *p_point, *p_gf0, *p_gf, *p_msf0, *p_msf, *p_part;
    cudaGetSymbolAddress(&p_idx,   g_idx);
    cudaGetSymbolAddress(&p_feat,  g_feat);
    cudaGetSymbolAddress(&p_point, g_point_t);
    cudaGetSymbolAddress(&p_gf0,   g_gf0_t);
    cudaGetSymbolAddress(&p_gf,    g_gf_t);
    cudaGetSymbolAddress(&p_msf0,  g_msf0_t);
    cudaGetSymbolAddress(&p_msf,   g_msf_t);
    cudaGetSymbolAddress(&p_part,  g_part);

    cudaFuncSetAttribute(feat_kernel,
                         cudaFuncAttributeMaxDynamicSharedMemorySize, SMEM_FEAT_BYTES);
    cudaFuncSetAttribute(gemm_mma,
                         cudaFuncAttributeMaxDynamicSharedMemorySize, SMEM_GEMM_BYTES);

    // 1) KNN
    knn_kernel<<<dim3(NPTS / 8, B), 256>>>(x, (int*)p_idx);

    // 2) per-point MLP features
    feat_kernel<<<dim3(NPTS / 128, 3, B), 128, SMEM_FEAT_BYTES>>>(
        x, sW0, sb0, sW1, sb1, sW2, sb2, (float*)p_feat, B);

    // 3) gather-max -> point_t[b][n][384]
    maxpool_kernel<<<dim3(NPTS / 8, 3, B), 256>>>(
        (const float*)p_feat, (const int*)p_idx, (float*)p_point, B);

    // 4) gf0_t[b][n][256] = relu(gW0 @ point)   M=256,K=384
    gemm_mma<<<dim3(256 / 128, NPTS / 128, B), 256, SMEM_GEMM_BYTES>>>(
        gW0, gb0, (const float*)p_point, (float*)p_gf0, 256, 384);

    // 5) gf_t[b][n][1024] = relu(gW1 @ gf0)     M=1024,K=256
    gemm_mma<<<dim3(1024 / 128, NPTS / 128, B), 256, SMEM_GEMM_BYTES>>>(
        gW1, gb1, (const float*)p_gf0, (float*)p_gf, 1024, 256);

    // 6) global_feature -> d_out[0 : B*1024]
    rowmax_part<<<dim3(1024 / 256, 16, B), 256>>>((const float*)p_gf, (float*)p_part);
    rowmax_fin<<<dim3(1024 / 256, B), 256>>>((const float*)p_part, out);

    // 7) msf0_t[b][n][256] = relu(mW0 @ gf)     M=256,K=1024
    gemm_mma<<<dim3(256 / 128, NPTS / 128, B), 256, SMEM_GEMM_BYTES>>>(
        mW0, mb0, (const float*)p_gf, (float*)p_msf0, 256, 1024);

    // 8) msf_t[b][n][128] = relu(mW1 @ msf0)    M=128,K=256
    gemm_mma<<<dim3(128 / 128, NPTS / 128, B), 256, SMEM_GEMM_BYTES>>>(
        mW1, mb1, (const float*)p_msf0, (float*)p_msf, 128, 256);

    // 9) transpose -> d_out[B*1024 : ] as [B,128,N]
    transpose_msf<<<dim3(NPTS / 32, 128 / 32, B), dim3(32, 8)>>>(
        (const float*)p_msf, out + (size_t)B * 1024);
}